// round 2
// baseline (speedup 1.0000x reference)
#include <cuda_runtime.h>
#include <math.h>

#define S_LEN   2048
#define BATCH   4
#define NHEAD   16
#define DK      64
#define DMODEL  1024
#define MTOK    (BATCH*S_LEN)   // 8192

// ---------------- scratch (static device globals; no allocations) ----------------
__device__ float g_Q[(size_t)BATCH*NHEAD*S_LEN*DK];
__device__ float g_K[(size_t)BATCH*NHEAD*S_LEN*DK];
__device__ float g_V[(size_t)BATCH*NHEAD*S_LEN*DK];
__device__ float g_O[(size_t)MTOK*DMODEL];
__device__ float g_rc[S_LEN*(DK/2)];
__device__ float g_rs[S_LEN*(DK/2)];

// ---------------- helpers ----------------
__device__ __forceinline__ unsigned f2tf(float x) {
    unsigned r;
    asm("cvt.rna.tf32.f32 %0, %1;" : "=r"(r) : "f"(x));
    return r;
}

__device__ __forceinline__ void mma8(float* c, const unsigned* a, const unsigned* b) {
    asm volatile(
        "mma.sync.aligned.m16n8k8.row.col.f32.tf32.tf32.f32 "
        "{%0,%1,%2,%3},{%4,%5,%6,%7},{%8,%9},{%0,%1,%2,%3};\n"
        : "+f"(c[0]), "+f"(c[1]), "+f"(c[2]), "+f"(c[3])
        : "r"(a[0]), "r"(a[1]), "r"(a[2]), "r"(a[3]), "r"(b[0]), "r"(b[1]));
}

// ---------------- RoPE table (double precision host-free init) ----------------
__global__ void rope_init_kernel() {
    int i = blockIdx.x * blockDim.x + threadIdx.x;
    if (i >= S_LEN * (DK/2)) return;
    int s = i >> 5;       // DK/2 == 32
    int j = i & 31;
    double invf = pow(10000.0, -((double)(2*j)) / (double)DK);
    double a = (double)s * invf;
    g_rc[i] = (float)cos(a);
    g_rs[i] = (float)sin(a);
}

// ---------------- 3xTF32 GEMM: C[M,N] = A[M,K] * B[K,N] ----------------
// MODE 0: plain row-major store.
// MODE 1: RoPE + scatter to [B,H,S,dk] (Q/K).
// MODE 2: scatter to [B,H,S,dk] (V).
template<int MODE>
__global__ void __launch_bounds__(256) gemm3_kernel(const float* __restrict__ A,
                                                    const float* __restrict__ B,
                                                    float* __restrict__ C) {
    const int N = DMODEL, K = DMODEL;
    __shared__ unsigned Ah[16][132], Al[16][132], Bh[16][132], Bl[16][132];

    const int tid  = threadIdx.x;
    const int lane = tid & 31;
    const int warp = tid >> 5;
    const int wm   = warp >> 1;   // 0..3
    const int wn   = warp & 1;    // 0..1
    const int gid  = lane >> 2;
    const int tig  = lane & 3;
    const int bm   = blockIdx.y * 128;
    const int bn   = blockIdx.x * 128;

    float acc[2][8][4];
#pragma unroll
    for (int mf = 0; mf < 2; mf++)
#pragma unroll
        for (int nf = 0; nf < 8; nf++)
#pragma unroll
            for (int c = 0; c < 4; c++) acc[mf][nf][c] = 0.f;

    for (int kt = 0; kt < K; kt += 16) {
        // A tile: 128 rows x 16 k -> transposed smem [k][m]
#pragma unroll
        for (int i = 0; i < 2; i++) {
            int lin = tid + i * 256;
            int row = lin >> 2;
            int c4  = (lin & 3) * 4;
            float4 v = *(const float4*)(A + (size_t)(bm + row) * K + kt + c4);
            float vv[4] = {v.x, v.y, v.z, v.w};
#pragma unroll
            for (int j = 0; j < 4; j++) {
                unsigned h = f2tf(vv[j]);
                Ah[c4 + j][row] = h;
                Al[c4 + j][row] = f2tf(vv[j] - __uint_as_float(h));
            }
        }
        // B tile: 16 k x 128 cols -> smem [k][n]
#pragma unroll
        for (int i = 0; i < 2; i++) {
            int lin = tid + i * 256;
            int row = lin >> 5;
            int c4  = (lin & 31) * 4;
            float4 v = *(const float4*)(B + (size_t)(kt + row) * N + bn + c4);
            float vv[4] = {v.x, v.y, v.z, v.w};
#pragma unroll
            for (int j = 0; j < 4; j++) {
                unsigned h = f2tf(vv[j]);
                Bh[row][c4 + j] = h;
                Bl[row][c4 + j] = f2tf(vv[j] - __uint_as_float(h));
            }
        }
        __syncthreads();

#pragma unroll
        for (int ks = 0; ks < 16; ks += 8) {
            unsigned ah[2][4], al[2][4], bh2[8][2], bl2[8][2];
#pragma unroll
            for (int mf = 0; mf < 2; mf++) {
                int mr = wm * 32 + mf * 16;
                ah[mf][0] = Ah[ks + tig][mr + gid];
                ah[mf][1] = Ah[ks + tig][mr + gid + 8];
                ah[mf][2] = Ah[ks + tig + 4][mr + gid];
                ah[mf][3] = Ah[ks + tig + 4][mr + gid + 8];
                al[mf][0] = Al[ks + tig][mr + gid];
                al[mf][1] = Al[ks + tig][mr + gid + 8];
                al[mf][2] = Al[ks + tig + 4][mr + gid];
                al[mf][3] = Al[ks + tig + 4][mr + gid + 8];
            }
#pragma unroll
            for (int nf = 0; nf < 8; nf++) {
                int nc = wn * 64 + nf * 8;
                bh2[nf][0] = Bh[ks + tig][nc + gid];
                bh2[nf][1] = Bh[ks + tig + 4][nc + gid];
                bl2[nf][0] = Bl[ks + tig][nc + gid];
                bl2[nf][1] = Bl[ks + tig + 4][nc + gid];
            }
#pragma unroll
            for (int mf = 0; mf < 2; mf++)
#pragma unroll
                for (int nf = 0; nf < 8; nf++) {
                    mma8(acc[mf][nf], al[mf], bh2[nf]);
                    mma8(acc[mf][nf], ah[mf], bl2[nf]);
                    mma8(acc[mf][nf], ah[mf], bh2[nf]);
                }
        }
        __syncthreads();
    }

    // epilogue
#pragma unroll
    for (int mf = 0; mf < 2; mf++) {
#pragma unroll
        for (int nf = 0; nf < 8; nf++) {
            int r0 = bm + wm * 32 + mf * 16 + gid;
            int nc = bn + wn * 64 + nf * 8 + tig * 2;
            if (MODE == 0) {
                C[(size_t)r0 * N + nc]           = acc[mf][nf][0];
                C[(size_t)r0 * N + nc + 1]       = acc[mf][nf][1];
                C[(size_t)(r0 + 8) * N + nc]     = acc[mf][nf][2];
                C[(size_t)(r0 + 8) * N + nc + 1] = acc[mf][nf][3];
            } else {
#pragma unroll
                for (int rr = 0; rr < 2; rr++) {
                    int r = r0 + rr * 8;
                    float v0 = acc[mf][nf][rr * 2];
                    float v1 = acc[mf][nf][rr * 2 + 1];
                    int b  = r >> 11;
                    int s  = r & (S_LEN - 1);
                    int h  = nc >> 6;
                    int dh = nc & 63;
                    float o0 = v0, o1 = v1;
                    if (MODE == 1) {
                        int j = dh >> 1;
                        float cs = g_rc[s * 32 + j];
                        float sn = g_rs[s * 32 + j];
                        o0 = v0 * cs - v1 * sn;
                        o1 = v1 * cs + v0 * sn;
                    }
                    size_t dst = ((size_t)(b * NHEAD + h) * S_LEN + s) * DK + dh;
                    C[dst]     = o0;
                    C[dst + 1] = o1;
                }
            }
        }
    }
}

// ---------------- flash attention (causal), Br=Bc=64, 3xTF32 MMA ----------------
#define ATTN_SMEM (8 * 64 * 68 * 4)

__global__ void __launch_bounds__(128) attn_kernel() {
    extern __shared__ unsigned smbuf[];
    unsigned* Qh = smbuf;
    unsigned* Ql = Qh + 64 * 68;
    unsigned* Kh = Ql + 64 * 68;
    unsigned* Kl = Kh + 64 * 68;
    unsigned* Vh = Kl + 64 * 68;
    unsigned* Vl = Vh + 64 * 68;
    unsigned* Ph = Vl + 64 * 68;
    unsigned* Pl = Ph + 64 * 68;

    const int qt   = blockIdx.x;
    const int bh   = blockIdx.y;
    const int tid  = threadIdx.x;
    const int lane = tid & 31;
    const int warp = tid >> 5;
    const int gid  = lane >> 2;
    const int tig  = lane & 3;
    const int mbase = warp * 16;

    const float* Qg = g_Q + (size_t)bh * S_LEN * DK;
    const float* Kg = g_K + (size_t)bh * S_LEN * DK;
    const float* Vg = g_V + (size_t)bh * S_LEN * DK;

    // load Q tile scaled by 1/sqrt(dk) = 1/8
#pragma unroll
    for (int i = 0; i < 8; i++) {
        int lin = tid + i * 128;
        int row = lin >> 4;
        int c4  = (lin & 15) * 4;
        float4 v = *(const float4*)(Qg + (size_t)(qt * 64 + row) * DK + c4);
        float vv[4] = {v.x * 0.125f, v.y * 0.125f, v.z * 0.125f, v.w * 0.125f};
#pragma unroll
        for (int j = 0; j < 4; j++) {
            unsigned h = f2tf(vv[j]);
            Qh[row * 68 + c4 + j] = h;
            Ql[row * 68 + c4 + j] = f2tf(vv[j] - __uint_as_float(h));
        }
    }

    float m0 = -1e30f, m1 = -1e30f, l0sum = 0.f, l1sum = 0.f;
    float o[8][4];
#pragma unroll
    for (int nf = 0; nf < 8; nf++)
#pragma unroll
        for (int c = 0; c < 4; c++) o[nf][c] = 0.f;

    const int rowg0 = qt * 64 + mbase + gid;
    const int rowg1 = rowg0 + 8;

    for (int kt = 0; kt <= qt; kt++) {
        __syncthreads();
        // load K,V tiles
#pragma unroll
        for (int i = 0; i < 8; i++) {
            int lin = tid + i * 128;
            int row = lin >> 4;
            int c4  = (lin & 15) * 4;
            float4 kv4 = *(const float4*)(Kg + (size_t)(kt * 64 + row) * DK + c4);
            float4 vv4 = *(const float4*)(Vg + (size_t)(kt * 64 + row) * DK + c4);
            float kk[4] = {kv4.x, kv4.y, kv4.z, kv4.w};
            float vv[4] = {vv4.x, vv4.y, vv4.z, vv4.w};
#pragma unroll
            for (int j = 0; j < 4; j++) {
                unsigned h = f2tf(kk[j]);
                Kh[row * 68 + c4 + j] = h;
                Kl[row * 68 + c4 + j] = f2tf(kk[j] - __uint_as_float(h));
                unsigned h2 = f2tf(vv[j]);
                Vh[row * 68 + c4 + j] = h2;
                Vl[row * 68 + c4 + j] = f2tf(vv[j] - __uint_as_float(h2));
            }
        }
        __syncthreads();

        // S = Q K^T (scaled)
        float sc[8][4];
#pragma unroll
        for (int nf = 0; nf < 8; nf++)
#pragma unroll
            for (int c = 0; c < 4; c++) sc[nf][c] = 0.f;

#pragma unroll
        for (int k8 = 0; k8 < 64; k8 += 8) {
            unsigned ah[4], al[4];
            ah[0] = Qh[(mbase + gid) * 68 + k8 + tig];
            ah[1] = Qh[(mbase + gid + 8) * 68 + k8 + tig];
            ah[2] = Qh[(mbase + gid) * 68 + k8 + tig + 4];
            ah[3] = Qh[(mbase + gid + 8) * 68 + k8 + tig + 4];
            al[0] = Ql[(mbase + gid) * 68 + k8 + tig];
            al[1] = Ql[(mbase + gid + 8) * 68 + k8 + tig];
            al[2] = Ql[(mbase + gid) * 68 + k8 + tig + 4];
            al[3] = Ql[(mbase + gid + 8) * 68 + k8 + tig + 4];
#pragma unroll
            for (int nf = 0; nf < 8; nf++) {
                unsigned bh2[2], bl2[2];
                bh2[0] = Kh[(nf * 8 + gid) * 68 + k8 + tig];
                bh2[1] = Kh[(nf * 8 + gid) * 68 + k8 + tig + 4];
                bl2[0] = Kl[(nf * 8 + gid) * 68 + k8 + tig];
                bl2[1] = Kl[(nf * 8 + gid) * 68 + k8 + tig + 4];
                mma8(sc[nf], al, bh2);
                mma8(sc[nf], ah, bl2);
                mma8(sc[nf], ah, bh2);
            }
        }

        // causal mask (diagonal tile only)
        if (kt == qt) {
#pragma unroll
            for (int nf = 0; nf < 8; nf++) {
                int cg = kt * 64 + nf * 8 + tig * 2;
                if (cg     > rowg0) sc[nf][0] = -1e30f;
                if (cg + 1 > rowg0) sc[nf][1] = -1e30f;
                if (cg     > rowg1) sc[nf][2] = -1e30f;
                if (cg + 1 > rowg1) sc[nf][3] = -1e30f;
            }
        }

        // online softmax
        float mx0 = -1e30f, mx1 = -1e30f;
#pragma unroll
        for (int nf = 0; nf < 8; nf++) {
            mx0 = fmaxf(mx0, fmaxf(sc[nf][0], sc[nf][1]));
            mx1 = fmaxf(mx1, fmaxf(sc[nf][2], sc[nf][3]));
        }
        mx0 = fmaxf(mx0, __shfl_xor_sync(0xffffffffu, mx0, 1));
        mx0 = fmaxf(mx0, __shfl_xor_sync(0xffffffffu, mx0, 2));
        mx1 = fmaxf(mx1, __shfl_xor_sync(0xffffffffu, mx1, 1));
        mx1 = fmaxf(mx1, __shfl_xor_sync(0xffffffffu, mx1, 2));

        float mn0 = fmaxf(m0, mx0), mn1 = fmaxf(m1, mx1);
        float a0 = expf(m0 - mn0), a1 = expf(m1 - mn1);
        float s0 = 0.f, s1 = 0.f;

        __syncwarp();
#pragma unroll
        for (int nf = 0; nf < 8; nf++) {
            float p00 = expf(sc[nf][0] - mn0);
            float p01 = expf(sc[nf][1] - mn0);
            float p10 = expf(sc[nf][2] - mn1);
            float p11 = expf(sc[nf][3] - mn1);
            s0 += p00 + p01;
            s1 += p10 + p11;
            int c0 = nf * 8 + tig * 2;
            unsigned h;
            h = f2tf(p00); Ph[(mbase + gid) * 68 + c0]     = h; Pl[(mbase + gid) * 68 + c0]     = f2tf(p00 - __uint_as_float(h));
            h = f2tf(p01); Ph[(mbase + gid) * 68 + c0 + 1] = h; Pl[(mbase + gid) * 68 + c0 + 1] = f2tf(p01 - __uint_as_float(h));
            h = f2tf(p10); Ph[(mbase + gid + 8) * 68 + c0]     = h; Pl[(mbase + gid + 8) * 68 + c0]     = f2tf(p10 - __uint_as_float(h));
            h = f2tf(p11); Ph[(mbase + gid + 8) * 68 + c0 + 1] = h; Pl[(mbase + gid + 8) * 68 + c0 + 1] = f2tf(p11 - __uint_as_float(h));
        }
        s0 += __shfl_xor_sync(0xffffffffu, s0, 1);
        s0 += __shfl_xor_sync(0xffffffffu, s0, 2);
        s1 += __shfl_xor_sync(0xffffffffu, s1, 1);
        s1 += __shfl_xor_sync(0xffffffffu, s1, 2);

        l0sum = l0sum * a0 + s0;
        l1sum = l1sum * a1 + s1;
        m0 = mn0;
        m1 = mn1;
#pragma unroll
        for (int nf = 0; nf < 8; nf++) {
            o[nf][0] *= a0; o[nf][1] *= a0;
            o[nf][2] *= a1; o[nf][3] *= a1;
        }
        __syncwarp();

        // O += P V
#pragma unroll
        for (int k8 = 0; k8 < 64; k8 += 8) {
            unsigned ah[4], al[4];
            ah[0] = Ph[(mbase + gid) * 68 + k8 + tig];
            ah[1] = Ph[(mbase + gid + 8) * 68 + k8 + tig];
            ah[2] = Ph[(mbase + gid) * 68 + k8 + tig + 4];
            ah[3] = Ph[(mbase + gid + 8) * 68 + k8 + tig + 4];
            al[0] = Pl[(mbase + gid) * 68 + k8 + tig];
            al[1] = Pl[(mbase + gid + 8) * 68 + k8 + tig];
            al[2] = Pl[(mbase + gid) * 68 + k8 + tig + 4];
            al[3] = Pl[(mbase + gid + 8) * 68 + k8 + tig + 4];
#pragma unroll
            for (int nf = 0; nf < 8; nf++) {
                unsigned bh2[2], bl2[2];
                bh2[0] = Vh[(k8 + tig) * 68 + nf * 8 + gid];
                bh2[1] = Vh[(k8 + tig + 4) * 68 + nf * 8 + gid];
                bl2[0] = Vl[(k8 + tig) * 68 + nf * 8 + gid];
                bl2[1] = Vl[(k8 + tig + 4) * 68 + nf * 8 + gid];
                mma8(o[nf], al, bh2);
                mma8(o[nf], ah, bl2);
                mma8(o[nf], ah, bh2);
            }
        }
    }

    // epilogue: normalize and scatter to [B,S,D]
    float il0 = 1.f / l0sum, il1 = 1.f / l1sum;
    int b = bh >> 4, h = bh & 15;
#pragma unroll
    for (int nf = 0; nf < 8; nf++) {
        int dh = nf * 8 + tig * 2;
        size_t d0 = ((size_t)(b * S_LEN + rowg0)) * DMODEL + h * 64 + dh;
        size_t d1 = ((size_t)(b * S_LEN + rowg1)) * DMODEL + h * 64 + dh;
        g_O[d0]     = o[nf][0] * il0;
        g_O[d0 + 1] = o[nf][1] * il0;
        g_O[d1]     = o[nf][2] * il1;
        g_O[d1 + 1] = o[nf][3] * il1;
    }
}

// ---------------- launch ----------------
extern "C" void kernel_launch(void* const* d_in, const int* in_sizes, int n_in,
                              void* d_out, int out_size) {
    (void)in_sizes; (void)n_in; (void)out_size;
    const float* x  = (const float*)d_in[0];
    const float* Wq = (const float*)d_in[1];
    const float* Wk = (const float*)d_in[2];
    const float* Wv = (const float*)d_in[3];
    const float* Wo = (const float*)d_in[4];
    float* out = (float*)d_out;

    float *Qp, *Kp, *Vp, *Op;
    cudaGetSymbolAddress((void**)&Qp, g_Q);
    cudaGetSymbolAddress((void**)&Kp, g_K);
    cudaGetSymbolAddress((void**)&Vp, g_V);
    cudaGetSymbolAddress((void**)&Op, g_O);

    rope_init_kernel<<<(S_LEN * (DK/2) + 255) / 256, 256>>>();

    dim3 ggrid(DMODEL / 128, MTOK / 128);
    gemm3_kernel<1><<<ggrid, 256>>>(x, Wq, Qp);
    gemm3_kernel<1><<<ggrid, 256>>>(x, Wk, Kp);
    gemm3_kernel<2><<<ggrid, 256>>>(x, Wv, Vp);

    cudaFuncSetAttribute(attn_kernel, cudaFuncAttributeMaxDynamicSharedMemorySize, ATTN_SMEM);
    attn_kernel<<<dim3(S_LEN / 64, BATCH * NHEAD), 128, ATTN_SMEM>>>();

    gemm3_kernel<0><<<ggrid, 256>>>(Op, Wo, out);
}

// round 3
// speedup vs baseline: 1.5110x; 1.5110x over previous
#include <cuda_runtime.h>
#include <math.h>

#define S_LEN   2048
#define BATCH   4
#define NHEAD   16
#define DK      64
#define DMODEL  1024
#define MTOK    (BATCH*S_LEN)   // 8192
#define QSCALE  0.18033688011112043f   // log2(e)/8

// ---------------- scratch ----------------
__device__ float g_XH[(size_t)MTOK*DMODEL];
__device__ float g_XL[(size_t)MTOK*DMODEL];
__device__ float g_WH[(size_t)4*DMODEL*DMODEL];
__device__ float g_WL[(size_t)4*DMODEL*DMODEL];
__device__ float g_QH[(size_t)MTOK*DMODEL];
__device__ float g_QL[(size_t)MTOK*DMODEL];
__device__ float g_KH[(size_t)MTOK*DMODEL];
__device__ float g_KL[(size_t)MTOK*DMODEL];
__device__ float g_V [(size_t)MTOK*DMODEL];
__device__ float g_OH[(size_t)MTOK*DMODEL];
__device__ float g_OL[(size_t)MTOK*DMODEL];
__device__ float g_rc[S_LEN*32];
__device__ float g_rs[S_LEN*32];

// ---------------- helpers ----------------
__device__ __forceinline__ unsigned f2tf(float x) {
    unsigned r;
    asm("cvt.rna.tf32.f32 %0, %1;" : "=r"(r) : "f"(x));
    return r;
}
__device__ __forceinline__ void mma8(float* c, const unsigned* a, const unsigned* b) {
    asm volatile(
        "mma.sync.aligned.m16n8k8.row.col.f32.tf32.tf32.f32 "
        "{%0,%1,%2,%3},{%4,%5,%6,%7},{%8,%9},{%0,%1,%2,%3};\n"
        : "+f"(c[0]), "+f"(c[1]), "+f"(c[2]), "+f"(c[3])
        : "r"(a[0]), "r"(a[1]), "r"(a[2]), "r"(a[3]), "r"(b[0]), "r"(b[1]));
}
__device__ __forceinline__ unsigned s2u(const void* p) {
    unsigned a;
    asm("{ .reg .u64 t; cvta.to.shared.u64 t, %1; cvt.u32.u64 %0, t; }" : "=r"(a) : "l"(p));
    return a;
}
#define CPA(d, s)  asm volatile("cp.async.cg.shared.global [%0], [%1], 16;\n" :: "r"(d), "l"(s))
#define CPCOMMIT() asm volatile("cp.async.commit_group;\n")
#define CPWAIT1()  asm volatile("cp.async.wait_group 1;\n")

// fast 2^x on fma/alu pipes (no MUFU). x <= 0 expected; rel err ~3e-6.
__device__ __forceinline__ float fexp2(float d) {
    d = fmaxf(d, -120.f);
    float r = d + 12582912.f;            // 1.5*2^23: integer in low mantissa bits
    int ib = __float_as_int(r);
    float f = d - (r - 12582912.f);      // f in [-0.5, 0.5]
    float p = 1.f + f*(0.69314718056f + f*(0.240226506959f + f*(0.0555041086648f +
              f*(0.00961812910763f + f*0.00133335581464f))));
    return __int_as_float(__float_as_int(p) + (ib << 23));
}

// ---------------- RoPE table ----------------
__global__ void rope_init_kernel() {
    int i = blockIdx.x * blockDim.x + threadIdx.x;
    if (i >= S_LEN * 32) return;
    int s = i >> 5, j = i & 31;
    double invf = pow(10000.0, -((double)(2*j)) / (double)DK);
    double a = (double)s * invf;
    g_rc[i] = (float)cos(a);
    g_rs[i] = (float)sin(a);
}

// ---------------- tf32 hi/lo pre-split ----------------
__global__ void split_kernel(const float4* __restrict__ s, float4* __restrict__ h,
                             float4* __restrict__ l, int n4) {
    int i = blockIdx.x * blockDim.x + threadIdx.x;
    if (i >= n4) return;
    float4 v = s[i];
    float4 hv, lv;
    hv.x = __uint_as_float(f2tf(v.x)); lv.x = __uint_as_float(f2tf(v.x - hv.x));
    hv.y = __uint_as_float(f2tf(v.y)); lv.y = __uint_as_float(f2tf(v.y - hv.y));
    hv.z = __uint_as_float(f2tf(v.z)); lv.z = __uint_as_float(f2tf(v.z - hv.z));
    hv.w = __uint_as_float(f2tf(v.w)); lv.w = __uint_as_float(f2tf(v.w - hv.w));
    h[i] = hv; l[i] = lv;
}

// ---------------- 3xTF32 GEMM, pre-split operands, cp.async double buffer ----------------
// MODE 0: plain fp32 store to C0.
// MODE 1: Q: RoPE + *QSCALE + split -> (C0=hi, C1=lo), scatter [B,H,S,dk]
// MODE 2: K: RoPE + split -> (C0, C1), scatter
// MODE 3: V: single tf32 -> C0, scatter
#define GEMM_ASZ (128*36)
#define GEMM_BSZ (32*136)
#define GEMM_STG (2*GEMM_ASZ + 2*GEMM_BSZ)       // 17920 words
#define GEMM_SMEM (2*GEMM_STG*4)                 // 143360 bytes

template<int MODE>
__global__ void __launch_bounds__(256) gemm_ps(const float* __restrict__ AH,
                                               const float* __restrict__ AL,
                                               const float* __restrict__ BH,
                                               const float* __restrict__ BL,
                                               float* __restrict__ C0,
                                               float* __restrict__ C1) {
    extern __shared__ unsigned sm[];
    const int tid = threadIdx.x, lane = tid & 31, warp = tid >> 5;
    const int wm = warp >> 1, wn = warp & 1, gid = lane >> 2, tig = lane & 3;
    const int bm = blockIdx.y * 128, bn = blockIdx.x * 128;
    unsigned sbase = s2u(sm);

    float acc[2][8][4];
#pragma unroll
    for (int mf = 0; mf < 2; mf++)
#pragma unroll
        for (int nf = 0; nf < 8; nf++)
#pragma unroll
            for (int c = 0; c < 4; c++) acc[mf][nf][c] = 0.f;

    auto load_stage = [&](int st, int k0) {
        unsigned ab = sbase + (unsigned)(st * GEMM_STG) * 4u;
#pragma unroll
        for (int i = 0; i < 4; i++) {
            int lin = tid + i * 256;
            int row = lin >> 3, c4 = (lin & 7) << 2;
            CPA(ab + (unsigned)(row*36 + c4)*4u,            AH + (size_t)(bm+row)*DMODEL + k0 + c4);
            CPA(ab + (unsigned)(GEMM_ASZ + row*36 + c4)*4u, AL + (size_t)(bm+row)*DMODEL + k0 + c4);
        }
#pragma unroll
        for (int i = 0; i < 4; i++) {
            int lin = tid + i * 256;
            int row = lin >> 5, c4 = (lin & 31) << 2;
            CPA(ab + (unsigned)(2*GEMM_ASZ + row*136 + c4)*4u,            BH + (size_t)(k0+row)*DMODEL + bn + c4);
            CPA(ab + (unsigned)(2*GEMM_ASZ + GEMM_BSZ + row*136 + c4)*4u, BL + (size_t)(k0+row)*DMODEL + bn + c4);
        }
    };

    load_stage(0, 0);
    CPCOMMIT();
    for (int kt = 0; kt < DMODEL / 32; kt++) {
        if (kt + 1 < DMODEL / 32) load_stage((kt + 1) & 1, (kt + 1) * 32);
        CPCOMMIT();
        CPWAIT1();
        __syncthreads();

        unsigned* As  = sm + (kt & 1) * GEMM_STG;
        unsigned* Alo = As + GEMM_ASZ;
        unsigned* Bs  = As + 2 * GEMM_ASZ;
        unsigned* Blo = Bs + GEMM_BSZ;

#pragma unroll
        for (int ks = 0; ks < 32; ks += 8) {
            unsigned ah[2][4], al[2][4];
#pragma unroll
            for (int mf = 0; mf < 2; mf++) {
                int mr = wm * 32 + mf * 16;
                ah[mf][0] = As [(mr+gid)  *36 + ks+tig];
                ah[mf][1] = As [(mr+gid+8)*36 + ks+tig];
                ah[mf][2] = As [(mr+gid)  *36 + ks+tig+4];
                ah[mf][3] = As [(mr+gid+8)*36 + ks+tig+4];
                al[mf][0] = Alo[(mr+gid)  *36 + ks+tig];
                al[mf][1] = Alo[(mr+gid+8)*36 + ks+tig];
                al[mf][2] = Alo[(mr+gid)  *36 + ks+tig+4];
                al[mf][3] = Alo[(mr+gid+8)*36 + ks+tig+4];
            }
#pragma unroll
            for (int nf = 0; nf < 8; nf++) {
                int nc = wn * 64 + nf * 8;
                unsigned bh2[2], bl2[2];
                bh2[0] = Bs [(ks+tig)  *136 + nc+gid];
                bh2[1] = Bs [(ks+tig+4)*136 + nc+gid];
                bl2[0] = Blo[(ks+tig)  *136 + nc+gid];
                bl2[1] = Blo[(ks+tig+4)*136 + nc+gid];
#pragma unroll
                for (int mf = 0; mf < 2; mf++) {
                    mma8(acc[mf][nf], al[mf], bh2);
                    mma8(acc[mf][nf], ah[mf], bl2);
                    mma8(acc[mf][nf], ah[mf], bh2);
                }
            }
        }
        __syncthreads();
    }

    // epilogue
#pragma unroll
    for (int mf = 0; mf < 2; mf++) {
#pragma unroll
        for (int nf = 0; nf < 8; nf++) {
            int r0 = bm + wm * 32 + mf * 16 + gid;
            int nc = bn + wn * 64 + nf * 8 + tig * 2;
            if (MODE == 0) {
                C0[(size_t)r0 * DMODEL + nc]           = acc[mf][nf][0];
                C0[(size_t)r0 * DMODEL + nc + 1]       = acc[mf][nf][1];
                C0[(size_t)(r0 + 8) * DMODEL + nc]     = acc[mf][nf][2];
                C0[(size_t)(r0 + 8) * DMODEL + nc + 1] = acc[mf][nf][3];
            } else {
#pragma unroll
                for (int rr = 0; rr < 2; rr++) {
                    int r = r0 + rr * 8;
                    float v0 = acc[mf][nf][rr * 2];
                    float v1 = acc[mf][nf][rr * 2 + 1];
                    int b = r >> 11, s = r & (S_LEN - 1);
                    int h = nc >> 6, dh = nc & 63;
                    if (MODE == 1 || MODE == 2) {
                        int j = dh >> 1;
                        float cs = g_rc[s * 32 + j], sn = g_rs[s * 32 + j];
                        float t0 = v0 * cs - v1 * sn;
                        float t1 = v1 * cs + v0 * sn;
                        v0 = t0; v1 = t1;
                    }
                    if (MODE == 1) { v0 *= QSCALE; v1 *= QSCALE; }
                    size_t dst = ((size_t)(b * NHEAD + h) * S_LEN + s) * DK + dh;
                    if (MODE == 3) {
                        C0[dst]     = __uint_as_float(f2tf(v0));
                        C0[dst + 1] = __uint_as_float(f2tf(v1));
                    } else {
                        float h0 = __uint_as_float(f2tf(v0));
                        float h1 = __uint_as_float(f2tf(v1));
                        C0[dst]     = h0;  C1[dst]     = __uint_as_float(f2tf(v0 - h0));
                        C0[dst + 1] = h1;  C1[dst + 1] = __uint_as_float(f2tf(v1 - h1));
                    }
                }
            }
        }
    }
}

// ---------------- flash attention: Br=128, Bc=64, 8 warps, cp.async double-buffered KV ----------------
// smem word offsets
#define AT_QH 0
#define AT_QL 8704
#define AT_P  17408
#define AT_KH 26112      // 2 stages x 4352
#define AT_KL 34816      // 2 stages x 4352
#define AT_V  43520      // 2 stages x 4608 (stride 72)
#define AT_WORDS 52736
#define AT_SMEM (AT_WORDS*4)

__global__ void __launch_bounds__(256) attn2_kernel() {
    extern __shared__ unsigned sm[];
    const int tid = threadIdx.x, lane = tid & 31, warp = tid >> 5;
    const int gid = lane >> 2, tig = lane & 3;
    const int qt = (gridDim.x - 1) - blockIdx.x;   // big tiles first
    const int bh = blockIdx.y;
    const int mb = warp * 16;
    unsigned sbase = s2u(sm);

    const float* QHg = g_QH + (size_t)bh * S_LEN * DK + (size_t)qt * 128 * DK;
    const float* QLg = g_QL + (size_t)bh * S_LEN * DK + (size_t)qt * 128 * DK;
    const float* KHg = g_KH + (size_t)bh * S_LEN * DK;
    const float* KLg = g_KL + (size_t)bh * S_LEN * DK;
    const float* Vg  = g_V  + (size_t)bh * S_LEN * DK;

    // Q tiles (one-time)
#pragma unroll
    for (int i = 0; i < 8; i++) {
        int lin = tid + i * 256;
        int row = lin >> 4, c4 = (lin & 15) << 2;
        CPA(sbase + (unsigned)(AT_QH + row*68 + c4)*4u, QHg + row*64 + c4);
        CPA(sbase + (unsigned)(AT_QL + row*68 + c4)*4u, QLg + row*64 + c4);
    }

    auto load_kv = [&](int st, int kt) {
        size_t off = (size_t)kt * 64 * DK;
#pragma unroll
        for (int i = 0; i < 4; i++) {
            int lin = tid + i * 256;
            int row = lin >> 4, c4 = (lin & 15) << 2;
            CPA(sbase + (unsigned)(AT_KH + st*4352 + row*68 + c4)*4u, KHg + off + row*64 + c4);
            CPA(sbase + (unsigned)(AT_KL + st*4352 + row*68 + c4)*4u, KLg + off + row*64 + c4);
            CPA(sbase + (unsigned)(AT_V  + st*4608 + row*72 + c4)*4u, Vg  + off + row*64 + c4);
        }
    };

    const int rowg0 = qt * 128 + mb + gid;
    const int rowg1 = rowg0 + 8;
    float m0 = -1e30f, m1 = -1e30f, l0 = 0.f, l1 = 0.f;
    float o[8][4];
#pragma unroll
    for (int nf = 0; nf < 8; nf++)
#pragma unroll
        for (int c = 0; c < 4; c++) o[nf][c] = 0.f;

    const int kmax = 2 * qt + 2;
    load_kv(0, 0);
    CPCOMMIT();

    for (int kt = 0; kt < kmax; kt++) {
        if (kt + 1 < kmax) load_kv((kt + 1) & 1, kt + 1);
        CPCOMMIT();
        CPWAIT1();
        __syncthreads();

        unsigned* QH_ = sm + AT_QH;
        unsigned* QL_ = sm + AT_QL;
        unsigned* P_  = sm + AT_P;
        unsigned* KH_ = sm + AT_KH + (kt & 1) * 4352;
        unsigned* KL_ = sm + AT_KL + (kt & 1) * 4352;
        unsigned* V_  = sm + AT_V  + (kt & 1) * 4608;

        // S = Q K^T (3xTF32, log2e/8 pre-folded)
        float sc[8][4];
#pragma unroll
        for (int nf = 0; nf < 8; nf++)
#pragma unroll
            for (int c = 0; c < 4; c++) sc[nf][c] = 0.f;

#pragma unroll
        for (int k8 = 0; k8 < 64; k8 += 8) {
            unsigned ah[4], al[4];
            ah[0] = QH_[(mb+gid)  *68 + k8+tig];
            ah[1] = QH_[(mb+gid+8)*68 + k8+tig];
            ah[2] = QH_[(mb+gid)  *68 + k8+tig+4];
            ah[3] = QH_[(mb+gid+8)*68 + k8+tig+4];
            al[0] = QL_[(mb+gid)  *68 + k8+tig];
            al[1] = QL_[(mb+gid+8)*68 + k8+tig];
            al[2] = QL_[(mb+gid)  *68 + k8+tig+4];
            al[3] = QL_[(mb+gid+8)*68 + k8+tig+4];
#pragma unroll
            for (int nf = 0; nf < 8; nf++) {
                unsigned bh2[2], bl2[2];
                bh2[0] = KH_[(nf*8+gid)*68 + k8+tig];
                bh2[1] = KH_[(nf*8+gid)*68 + k8+tig+4];
                bl2[0] = KL_[(nf*8+gid)*68 + k8+tig];
                bl2[1] = KL_[(nf*8+gid)*68 + k8+tig+4];
                mma8(sc[nf], al, bh2);
                mma8(sc[nf], ah, bl2);
                mma8(sc[nf], ah, bh2);
            }
        }

        if (kt >= 2 * qt) {   // diagonal tiles
#pragma unroll
            for (int nf = 0; nf < 8; nf++) {
                int cg = kt * 64 + nf * 8 + tig * 2;
                if (cg     > rowg0) sc[nf][0] = -1e30f;
                if (cg + 1 > rowg0) sc[nf][1] = -1e30f;
                if (cg     > rowg1) sc[nf][2] = -1e30f;
                if (cg + 1 > rowg1) sc[nf][3] = -1e30f;
            }
        }

        // online softmax (base-2 domain), fast exp2
        float mx0 = -1e30f, mx1 = -1e30f;
#pragma unroll
        for (int nf = 0; nf < 8; nf++) {
            mx0 = fmaxf(mx0, fmaxf(sc[nf][0], sc[nf][1]));
            mx1 = fmaxf(mx1, fmaxf(sc[nf][2], sc[nf][3]));
        }
        mx0 = fmaxf(mx0, __shfl_xor_sync(0xffffffffu, mx0, 1));
        mx0 = fmaxf(mx0, __shfl_xor_sync(0xffffffffu, mx0, 2));
        mx1 = fmaxf(mx1, __shfl_xor_sync(0xffffffffu, mx1, 1));
        mx1 = fmaxf(mx1, __shfl_xor_sync(0xffffffffu, mx1, 2));

        float mn0 = fmaxf(m0, mx0), mn1 = fmaxf(m1, mx1);
        float a0 = fexp2(m0 - mn0), a1 = fexp2(m1 - mn1);
        float s0 = 0.f, s1 = 0.f;

#pragma unroll
        for (int nf = 0; nf < 8; nf++) {
            float p00 = fexp2(sc[nf][0] - mn0);
            float p01 = fexp2(sc[nf][1] - mn0);
            float p10 = fexp2(sc[nf][2] - mn1);
            float p11 = fexp2(sc[nf][3] - mn1);
            s0 += p00 + p01;
            s1 += p10 + p11;
            int c0 = nf * 8 + tig * 2;
            *(uint2*)&P_[(mb+gid)  *68 + c0] = make_uint2(f2tf(p00), f2tf(p01));
            *(uint2*)&P_[(mb+gid+8)*68 + c0] = make_uint2(f2tf(p10), f2tf(p11));
        }
        s0 += __shfl_xor_sync(0xffffffffu, s0, 1);
        s0 += __shfl_xor_sync(0xffffffffu, s0, 2);
        s1 += __shfl_xor_sync(0xffffffffu, s1, 1);
        s1 += __shfl_xor_sync(0xffffffffu, s1, 2);

        l0 = l0 * a0 + s0;
        l1 = l1 * a1 + s1;
        m0 = mn0; m1 = mn1;
#pragma unroll
        for (int nf = 0; nf < 8; nf++) {
            o[nf][0] *= a0; o[nf][1] *= a0;
            o[nf][2] *= a1; o[nf][3] *= a1;
        }
        __syncwarp();

        // O += P V (single tf32)
#pragma unroll
        for (int k8 = 0; k8 < 64; k8 += 8) {
            unsigned ap[4];
            ap[0] = P_[(mb+gid)  *68 + k8+tig];
            ap[1] = P_[(mb+gid+8)*68 + k8+tig];
            ap[2] = P_[(mb+gid)  *68 + k8+tig+4];
            ap[3] = P_[(mb+gid+8)*68 + k8+tig+4];
#pragma unroll
            for (int nf = 0; nf < 8; nf++) {
                unsigned bv[2];
                bv[0] = V_[(k8+tig)  *72 + nf*8+gid];
                bv[1] = V_[(k8+tig+4)*72 + nf*8+gid];
                mma8(o[nf], ap, bv);
            }
        }
        __syncthreads();
    }

    // epilogue: normalize, split hi/lo, scatter to [B,S,D]
    float il0 = 1.f / l0, il1 = 1.f / l1;
    int b = bh >> 4, h = bh & 15;
#pragma unroll
    for (int nf = 0; nf < 8; nf++) {
        int dh = nf * 8 + tig * 2;
        size_t d0 = ((size_t)(b * S_LEN + rowg0)) * DMODEL + h * 64 + dh;
        size_t d1 = ((size_t)(b * S_LEN + rowg1)) * DMODEL + h * 64 + dh;
        float v;
        v = o[nf][0] * il0; { float hh = __uint_as_float(f2tf(v)); g_OH[d0]   = hh; g_OL[d0]   = __uint_as_float(f2tf(v - hh)); }
        v = o[nf][1] * il0; { float hh = __uint_as_float(f2tf(v)); g_OH[d0+1] = hh; g_OL[d0+1] = __uint_as_float(f2tf(v - hh)); }
        v = o[nf][2] * il1; { float hh = __uint_as_float(f2tf(v)); g_OH[d1]   = hh; g_OL[d1]   = __uint_as_float(f2tf(v - hh)); }
        v = o[nf][3] * il1; { float hh = __uint_as_float(f2tf(v)); g_OH[d1+1] = hh; g_OL[d1+1] = __uint_as_float(f2tf(v - hh)); }
    }
}

// ---------------- launch ----------------
extern "C" void kernel_launch(void* const* d_in, const int* in_sizes, int n_in,
                              void* d_out, int out_size) {
    (void)in_sizes; (void)n_in; (void)out_size;
    const float* x  = (const float*)d_in[0];
    const float* Wq = (const float*)d_in[1];
    const float* Wk = (const float*)d_in[2];
    const float* Wv = (const float*)d_in[3];
    const float* Wo = (const float*)d_in[4];
    float* out = (float*)d_out;

    float *XH, *XL, *WH, *WL, *QH, *QL, *KH, *KL, *V, *OH, *OL;
    cudaGetSymbolAddress((void**)&XH, g_XH);
    cudaGetSymbolAddress((void**)&XL, g_XL);
    cudaGetSymbolAddress((void**)&WH, g_WH);
    cudaGetSymbolAddress((void**)&WL, g_WL);
    cudaGetSymbolAddress((void**)&QH, g_QH);
    cudaGetSymbolAddress((void**)&QL, g_QL);
    cudaGetSymbolAddress((void**)&KH, g_KH);
    cudaGetSymbolAddress((void**)&KL, g_KL);
    cudaGetSymbolAddress((void**)&V,  g_V);
    cudaGetSymbolAddress((void**)&OH, g_OH);
    cudaGetSymbolAddress((void**)&OL, g_OL);

    cudaFuncSetAttribute(gemm_ps<0>, cudaFuncAttributeMaxDynamicSharedMemorySize, GEMM_SMEM);
    cudaFuncSetAttribute(gemm_ps<1>, cudaFuncAttributeMaxDynamicSharedMemorySize, GEMM_SMEM);
    cudaFuncSetAttribute(gemm_ps<2>, cudaFuncAttributeMaxDynamicSharedMemorySize, GEMM_SMEM);
    cudaFuncSetAttribute(gemm_ps<3>, cudaFuncAttributeMaxDynamicSharedMemorySize, GEMM_SMEM);
    cudaFuncSetAttribute(attn2_kernel, cudaFuncAttributeMaxDynamicSharedMemorySize, AT_SMEM);

    rope_init_kernel<<<(S_LEN * 32 + 255) / 256, 256>>>();

    const int NX4 = MTOK * DMODEL / 4;
    const int NW4 = DMODEL * DMODEL / 4;
    const size_t WSTEP = (size_t)DMODEL * DMODEL;
    split_kernel<<<(NX4 + 255) / 256, 256>>>((const float4*)x, (float4*)XH, (float4*)XL, NX4);
    split_kernel<<<(NW4 + 255) / 256, 256>>>((const float4*)Wq, (float4*)(WH + 0*WSTEP), (float4*)(WL + 0*WSTEP), NW4);
    split_kernel<<<(NW4 + 255) / 256, 256>>>((const float4*)Wk, (float4*)(WH + 1*WSTEP), (float4*)(WL + 1*WSTEP), NW4);
    split_kernel<<<(NW4 + 255) / 256, 256>>>((const float4*)Wv, (float4*)(WH + 2*WSTEP), (float4*)(WL + 2*WSTEP), NW4);
    split_kernel<<<(NW4 + 255) / 256, 256>>>((const float4*)Wo, (float4*)(WH + 3*WSTEP), (float4*)(WL + 3*WSTEP), NW4);

    dim3 ggrid(DMODEL / 128, MTOK / 128);
    gemm_ps<1><<<ggrid, 256, GEMM_SMEM>>>(XH, XL, WH + 0*WSTEP, WL + 0*WSTEP, QH, QL);
    gemm_ps<2><<<ggrid, 256, GEMM_SMEM>>>(XH, XL, WH + 1*WSTEP, WL + 1*WSTEP, KH, KL);
    gemm_ps<3><<<ggrid, 256, GEMM_SMEM>>>(XH, XL, WH + 2*WSTEP, WL + 2*WSTEP, V, nullptr);

    attn2_kernel<<<dim3(S_LEN / 128, BATCH * NHEAD), 256, AT_SMEM>>>();

    gemm_ps<0><<<ggrid, 256, GEMM_SMEM>>>(OH, OL, WH + 3*WSTEP, WL + 3*WSTEP, out, nullptr);
}

// round 6
// speedup vs baseline: 2.4252x; 1.6051x over previous
#include <cuda_runtime.h>
#include <cuda_bf16.h>
#include <math.h>

#define S_LEN   2048
#define BATCH   4
#define NHEAD   16
#define DK      64
#define DMODEL  1024
#define MTOK    (BATCH*S_LEN)   // 8192
#define QSCALE  0.18033688011112043f   // log2(e)/8

// ---------------- scratch ----------------
__device__ __nv_bfloat16 g_XHb[(size_t)MTOK*DMODEL];
__device__ __nv_bfloat16 g_XLb[(size_t)MTOK*DMODEL];
__device__ __nv_bfloat16 g_WTH[(size_t)4*DMODEL*DMODEL];   // W transposed [N,K], bf16 hi
__device__ __nv_bfloat16 g_WTL[(size_t)4*DMODEL*DMODEL];   // bf16 lo
__device__ __nv_bfloat16 g_QHb[(size_t)MTOK*DMODEL];
__device__ __nv_bfloat16 g_QLb[(size_t)MTOK*DMODEL];
__device__ __nv_bfloat16 g_KHb[(size_t)MTOK*DMODEL];
__device__ __nv_bfloat16 g_KLb[(size_t)MTOK*DMODEL];
__device__ __nv_bfloat16 g_OHb[(size_t)MTOK*DMODEL];
__device__ __nv_bfloat16 g_OLb[(size_t)MTOK*DMODEL];
__device__ float g_V [(size_t)MTOK*DMODEL];
__device__ float g_rc[S_LEN*32];
__device__ float g_rs[S_LEN*32];

// ---------------- helpers ----------------
__device__ __forceinline__ unsigned f2tf(float x) {
    unsigned r;
    asm("cvt.rna.tf32.f32 %0, %1;" : "=r"(r) : "f"(x));
    return r;
}
// tf32 m16n8k8 (PV path)
__device__ __forceinline__ void mma8(float* c, const unsigned* a, const unsigned* b) {
    asm volatile(
        "mma.sync.aligned.m16n8k8.row.col.f32.tf32.tf32.f32 "
        "{%0,%1,%2,%3},{%4,%5,%6,%7},{%8,%9},{%0,%1,%2,%3};\n"
        : "+f"(c[0]), "+f"(c[1]), "+f"(c[2]), "+f"(c[3])
        : "r"(a[0]), "r"(a[1]), "r"(a[2]), "r"(a[3]), "r"(b[0]), "r"(b[1]));
}
// bf16 m16n8k16 (GEMM + scores): each 32-bit reg = bf16 k-pair
__device__ __forceinline__ void mma16(float* c, const unsigned* a, const unsigned* b) {
    asm volatile(
        "mma.sync.aligned.m16n8k16.row.col.f32.bf16.bf16.f32 "
        "{%0,%1,%2,%3},{%4,%5,%6,%7},{%8,%9},{%0,%1,%2,%3};\n"
        : "+f"(c[0]), "+f"(c[1]), "+f"(c[2]), "+f"(c[3])
        : "r"(a[0]), "r"(a[1]), "r"(a[2]), "r"(a[3]), "r"(b[0]), "r"(b[1]));
}
__device__ __forceinline__ unsigned s2u(const void* p) {
    unsigned a;
    asm("{ .reg .u64 t; cvta.to.shared.u64 t, %1; cvt.u32.u64 %0, t; }" : "=r"(a) : "l"(p));
    return a;
}
#define CPA(d, s)  asm volatile("cp.async.cg.shared.global [%0], [%1], 16;\n" :: "r"(d), "l"(s))
#define CPCOMMIT() asm volatile("cp.async.commit_group;\n")
#define CPWAIT0()  asm volatile("cp.async.wait_group 0;\n")
#define CPWAIT1()  asm volatile("cp.async.wait_group 1;\n")

// fast 2^x on fma/alu pipes (no MUFU)
__device__ __forceinline__ float fexp2(float d) {
    d = fmaxf(d, -120.f);
    float r = d + 12582912.f;
    int ib = __float_as_int(r);
    float f = d - (r - 12582912.f);
    float p = 1.f + f*(0.69314718056f + f*(0.240226506959f + f*(0.0555041086648f +
              f*(0.00961812910763f + f*0.00133335581464f))));
    return __int_as_float(__float_as_int(p) + (ib << 23));
}

// ---------------- RoPE table ----------------
__global__ void rope_init_kernel() {
    int i = blockIdx.x * blockDim.x + threadIdx.x;
    if (i >= S_LEN * 32) return;
    int s = i >> 5, j = i & 31;
    double invf = pow(10000.0, -((double)(2*j)) / (double)DK);
    double a = (double)s * invf;
    g_rc[i] = (float)cos(a);
    g_rs[i] = (float)sin(a);
}

// ---------------- x -> bf16 hi/lo ----------------
__global__ void xsplit_kernel(const float4* __restrict__ X, __nv_bfloat16* __restrict__ H,
                              __nv_bfloat16* __restrict__ L, int n4) {
    int i = blockIdx.x * blockDim.x + threadIdx.x;
    if (i >= n4) return;
    float4 v = X[i];
    __nv_bfloat16 h0 = __float2bfloat16(v.x), h1 = __float2bfloat16(v.y);
    __nv_bfloat16 h2 = __float2bfloat16(v.z), h3 = __float2bfloat16(v.w);
    __nv_bfloat162* Hp = (__nv_bfloat162*)(H + (size_t)i * 4);
    __nv_bfloat162* Lp = (__nv_bfloat162*)(L + (size_t)i * 4);
    Hp[0] = __nv_bfloat162(h0, h1);
    Hp[1] = __nv_bfloat162(h2, h3);
    Lp[0] = __nv_bfloat162(__float2bfloat16(v.x - __bfloat162float(h0)),
                           __float2bfloat16(v.y - __bfloat162float(h1)));
    Lp[1] = __nv_bfloat162(__float2bfloat16(v.z - __bfloat162float(h2)),
                           __float2bfloat16(v.w - __bfloat162float(h3)));
}

// ---------------- W[K,N] -> WT[N,K] bf16 hi/lo ----------------
__global__ void wtrans_kernel(const float* __restrict__ W, __nv_bfloat16* __restrict__ TH,
                              __nv_bfloat16* __restrict__ TL) {
    __shared__ float t[32][33];
    int n0 = blockIdx.x * 32, k0 = blockIdx.y * 32;
    int tx = threadIdx.x, ty = threadIdx.y;
#pragma unroll
    for (int j = 0; j < 32; j += 8)
        t[ty + j][tx] = W[(size_t)(k0 + ty + j) * DMODEL + n0 + tx];
    __syncthreads();
#pragma unroll
    for (int j = 0; j < 32; j += 8) {
        float v = t[tx][ty + j];
        int n = n0 + ty + j, k = k0 + tx;
        __nv_bfloat16 hv = __float2bfloat16(v);
        TH[(size_t)n * DMODEL + k] = hv;
        TL[(size_t)n * DMODEL + k] = __float2bfloat16(v - __bfloat162float(hv));
    }
}

// ---------------- 3xBF16 GEMM: C[M,N] = A[M,K] * B[N,K]^T, KT=32/stage, 2-stage cp.async ----------------
// MODE 0: fp32 store. MODE 1: Q rope+scale+bf16split scatter. MODE 2: K rope+bf16split. MODE 3: V tf32 fp32 scatter.
#define GS 20
#define GW_AH 0
#define GW_AL 2560
#define GW_BH 5120
#define GW_BL 7680
#define GW_STG 10240
#define G_SMEM (2*GW_STG*4)   // 81920 bytes -> 2 CTAs/SM

template<int MODE>
__global__ void __launch_bounds__(256, 2) gemm_bf(const __nv_bfloat16* __restrict__ AH,
                                                  const __nv_bfloat16* __restrict__ AL,
                                                  const __nv_bfloat16* __restrict__ BH,
                                                  const __nv_bfloat16* __restrict__ BL,
                                                  void* __restrict__ C0v,
                                                  void* __restrict__ C1v) {
    extern __shared__ unsigned sm[];
    const int tid = threadIdx.x, lane = tid & 31, warp = tid >> 5;
    const int wm = warp >> 1, wn = warp & 1, gid = lane >> 2, tig = lane & 3;
    const int bm = blockIdx.y * 128, bn = blockIdx.x * 128;
    unsigned sbase = s2u(sm);

    float acc[2][8][4];
#pragma unroll
    for (int mf = 0; mf < 2; mf++)
#pragma unroll
        for (int nf = 0; nf < 8; nf++)
#pragma unroll
            for (int c = 0; c < 4; c++) acc[mf][nf][c] = 0.f;

    auto load_stage = [&](int st, int k0) {
        unsigned stb = sbase + (unsigned)(st * GW_STG) * 4u;
#pragma unroll
        for (int i = 0; i < 2; i++) {
            int lin = tid + i * 256;                 // 0..511
            int row = lin >> 2, ck = lin & 3;        // 128 rows x 4 chunks (16B = 8 bf16)
            unsigned wo = (unsigned)(row * GS + ck * 4) * 4u;
            CPA(stb + GW_AH*4u + wo, AH + (size_t)(bm + row) * DMODEL + k0 + ck * 8);
            CPA(stb + GW_AL*4u + wo, AL + (size_t)(bm + row) * DMODEL + k0 + ck * 8);
            CPA(stb + GW_BH*4u + wo, BH + (size_t)(bn + row) * DMODEL + k0 + ck * 8);
            CPA(stb + GW_BL*4u + wo, BL + (size_t)(bn + row) * DMODEL + k0 + ck * 8);
        }
    };

    load_stage(0, 0);
    CPCOMMIT();
    for (int kt = 0; kt < 32; kt++) {
        if (kt + 1 < 32) {
            load_stage((kt + 1) & 1, (kt + 1) * 32);
            CPCOMMIT();
            CPWAIT1();
        } else {
            CPWAIT0();
        }
        __syncthreads();

        unsigned* As  = sm + (kt & 1) * GW_STG;
        unsigned* Alo = As + GW_AL;
        unsigned* Bs  = As + GW_BH;
        unsigned* Blo = As + GW_BL;

#pragma unroll
        for (int ks = 0; ks < 2; ks++) {
            unsigned ah[2][4], al[2][4];
#pragma unroll
            for (int mf = 0; mf < 2; mf++) {
                int mr = wm * 32 + mf * 16;
                ah[mf][0] = As [(mr+gid)  *GS + ks*8 + tig];
                ah[mf][1] = As [(mr+gid+8)*GS + ks*8 + tig];
                ah[mf][2] = As [(mr+gid)  *GS + ks*8 + tig+4];
                ah[mf][3] = As [(mr+gid+8)*GS + ks*8 + tig+4];
                al[mf][0] = Alo[(mr+gid)  *GS + ks*8 + tig];
                al[mf][1] = Alo[(mr+gid+8)*GS + ks*8 + tig];
                al[mf][2] = Alo[(mr+gid)  *GS + ks*8 + tig+4];
                al[mf][3] = Alo[(mr+gid+8)*GS + ks*8 + tig+4];
            }
#pragma unroll
            for (int nf = 0; nf < 8; nf++) {
                int nc = wn * 64 + nf * 8;
                unsigned bh2[2], bl2[2];
                bh2[0] = Bs [(nc+gid)*GS + ks*8 + tig];
                bh2[1] = Bs [(nc+gid)*GS + ks*8 + tig+4];
                bl2[0] = Blo[(nc+gid)*GS + ks*8 + tig];
                bl2[1] = Blo[(nc+gid)*GS + ks*8 + tig+4];
#pragma unroll
                for (int mf = 0; mf < 2; mf++) {
                    mma16(acc[mf][nf], al[mf], bh2);
                    mma16(acc[mf][nf], ah[mf], bl2);
                    mma16(acc[mf][nf], ah[mf], bh2);
                }
            }
        }
        __syncthreads();
    }

    // epilogue
    float* C0f = (float*)C0v;
    __nv_bfloat16* C0b = (__nv_bfloat16*)C0v;
    __nv_bfloat16* C1b = (__nv_bfloat16*)C1v;
#pragma unroll
    for (int mf = 0; mf < 2; mf++) {
#pragma unroll
        for (int nf = 0; nf < 8; nf++) {
            int r0 = bm + wm * 32 + mf * 16 + gid;
            int nc = bn + wn * 64 + nf * 8 + tig * 2;
            if (MODE == 0) {
                C0f[(size_t)r0 * DMODEL + nc]           = acc[mf][nf][0];
                C0f[(size_t)r0 * DMODEL + nc + 1]       = acc[mf][nf][1];
                C0f[(size_t)(r0 + 8) * DMODEL + nc]     = acc[mf][nf][2];
                C0f[(size_t)(r0 + 8) * DMODEL + nc + 1] = acc[mf][nf][3];
            } else {
#pragma unroll
                for (int rr = 0; rr < 2; rr++) {
                    int r = r0 + rr * 8;
                    float v0 = acc[mf][nf][rr * 2];
                    float v1 = acc[mf][nf][rr * 2 + 1];
                    int b = r >> 11, s = r & (S_LEN - 1);
                    int h = nc >> 6, dh = nc & 63;
                    if (MODE == 1 || MODE == 2) {
                        int j = dh >> 1;
                        float cs = g_rc[s * 32 + j], sn = g_rs[s * 32 + j];
                        float t0 = v0 * cs - v1 * sn;
                        float t1 = v1 * cs + v0 * sn;
                        v0 = t0; v1 = t1;
                    }
                    if (MODE == 1) { v0 *= QSCALE; v1 *= QSCALE; }
                    size_t dst = ((size_t)(b * NHEAD + h) * S_LEN + s) * DK + dh;
                    if (MODE == 3) {
                        C0f[dst]     = __uint_as_float(f2tf(v0));
                        C0f[dst + 1] = __uint_as_float(f2tf(v1));
                    } else {
                        __nv_bfloat16 h0 = __float2bfloat16(v0);
                        __nv_bfloat16 h1 = __float2bfloat16(v1);
                        *(__nv_bfloat162*)(C0b + dst) = __nv_bfloat162(h0, h1);
                        *(__nv_bfloat162*)(C1b + dst) = __nv_bfloat162(
                            __float2bfloat16(v0 - __bfloat162float(h0)),
                            __float2bfloat16(v1 - __bfloat162float(h1)));
                    }
                }
            }
        }
    }
}

// ---------------- flash attention: Br=128, Bc=64, bf16 3x scores + tf32 PV ----------------
#define AT_QH 0                       // 128 x 36
#define AT_QL 4608
#define AT_P  9216                    // 128 x 68
#define AT_KH 17920                   // 2 stages x (64 x 36)
#define AT_KL 22528
#define AT_V  27136                   // 2 stages x (64 x 72)
#define AT_WORDS 36352
#define AT_SMEM (AT_WORDS*4)          // 145408 bytes

__global__ void __launch_bounds__(256) attn2_kernel() {
    extern __shared__ unsigned sm[];
    const int tid = threadIdx.x, lane = tid & 31, warp = tid >> 5;
    const int gid = lane >> 2, tig = lane & 3;
    const int qt = (gridDim.x - 1) - blockIdx.x;
    const int bh = blockIdx.y;
    const int mb = warp * 16;
    unsigned sbase = s2u(sm);

    const __nv_bfloat16* QHg = g_QHb + (size_t)bh * S_LEN * DK + (size_t)qt * 128 * DK;
    const __nv_bfloat16* QLg = g_QLb + (size_t)bh * S_LEN * DK + (size_t)qt * 128 * DK;
    const __nv_bfloat16* KHg = g_KHb + (size_t)bh * S_LEN * DK;
    const __nv_bfloat16* KLg = g_KLb + (size_t)bh * S_LEN * DK;
    const float*         Vg  = g_V   + (size_t)bh * S_LEN * DK;

    // Q tiles: 128 rows x 8 chunks(16B) per array
#pragma unroll
    for (int i = 0; i < 4; i++) {
        int lin = tid + i * 256;
        int row = lin >> 3, ck = lin & 7;
        unsigned wo = (unsigned)(row * 36 + ck * 4) * 4u;
        CPA(sbase + AT_QH*4u + wo, QHg + row * 64 + ck * 8);
        CPA(sbase + AT_QL*4u + wo, QLg + row * 64 + ck * 8);
    }

    auto load_kv = [&](int st, int kt) {
        size_t off = (size_t)kt * 64 * DK;
#pragma unroll
        for (int i = 0; i < 2; i++) {
            int lin = tid + i * 256;
            int row = lin >> 3, ck = lin & 7;
            unsigned wo = (unsigned)(row * 36 + ck * 4) * 4u;
            CPA(sbase + (AT_KH + st*2304)*4u + wo, KHg + off + row * 64 + ck * 8);
            CPA(sbase + (AT_KL + st*2304)*4u + wo, KLg + off + row * 64 + ck * 8);
        }
#pragma unroll
        for (int i = 0; i < 4; i++) {
            int lin = tid + i * 256;
            int row = lin >> 4, c4 = (lin & 15) << 2;
            CPA(sbase + (AT_V + st*4608)*4u + (unsigned)(row * 72 + c4) * 4u,
                Vg + off + row * 64 + c4);
        }
    };

    const int rowg0 = qt * 128 + mb + gid;
    const int rowg1 = rowg0 + 8;
    float m0 = -1e30f, m1 = -1e30f, l0 = 0.f, l1 = 0.f;
    float o[8][4];
#pragma unroll
    for (int nf = 0; nf < 8; nf++)
#pragma unroll
        for (int c = 0; c < 4; c++) o[nf][c] = 0.f;

    const int kmax = 2 * qt + 2;
    load_kv(0, 0);
    CPCOMMIT();

    for (int kt = 0; kt < kmax; kt++) {
        if (kt + 1 < kmax) load_kv((kt + 1) & 1, kt + 1);
        CPCOMMIT();
        CPWAIT1();
        __syncthreads();

        unsigned* QH_ = sm + AT_QH;
        unsigned* QL_ = sm + AT_QL;
        unsigned* P_  = sm + AT_P;
        unsigned* KH_ = sm + AT_KH + (kt & 1) * 2304;
        unsigned* KL_ = sm + AT_KL + (kt & 1) * 2304;
        unsigned* V_  = sm + AT_V  + (kt & 1) * 4608;

        // S = Q K^T (3xBF16, k16)
        float sc[8][4];
#pragma unroll
        for (int nf = 0; nf < 8; nf++)
#pragma unroll
            for (int c = 0; c < 4; c++) sc[nf][c] = 0.f;

#pragma unroll
        for (int ks = 0; ks < 4; ks++) {
            unsigned ah[4], al[4];
            ah[0] = QH_[(mb+gid)  *36 + ks*8 + tig];
            ah[1] = QH_[(mb+gid+8)*36 + ks*8 + tig];
            ah[2] = QH_[(mb+gid)  *36 + ks*8 + tig+4];
            ah[3] = QH_[(mb+gid+8)*36 + ks*8 + tig+4];
            al[0] = QL_[(mb+gid)  *36 + ks*8 + tig];
            al[1] = QL_[(mb+gid+8)*36 + ks*8 + tig];
            al[2] = QL_[(mb+gid)  *36 + ks*8 + tig+4];
            al[3] = QL_[(mb+gid+8)*36 + ks*8 + tig+4];
#pragma unroll
            for (int nf = 0; nf < 8; nf++) {
                unsigned bh2[2], bl2[2];
                bh2[0] = KH_[(nf*8+gid)*36 + ks*8 + tig];
                bh2[1] = KH_[(nf*8+gid)*36 + ks*8 + tig+4];
                bl2[0] = KL_[(nf*8+gid)*36 + ks*8 + tig];
                bl2[1] = KL_[(nf*8+gid)*36 + ks*8 + tig+4];
                mma16(sc[nf], al, bh2);
                mma16(sc[nf], ah, bl2);
                mma16(sc[nf], ah, bh2);
            }
        }

        if (kt >= 2 * qt) {    // diagonal tiles
#pragma unroll
            for (int nf = 0; nf < 8; nf++) {
                int cg = kt * 64 + nf * 8 + tig * 2;
                if (cg     > rowg0) sc[nf][0] = -1e30f;
                if (cg + 1 > rowg0) sc[nf][1] = -1e30f;
                if (cg     > rowg1) sc[nf][2] = -1e30f;
                if (cg + 1 > rowg1) sc[nf][3] = -1e30f;
            }
        }

        // online softmax (base-2)
        float mx0 = -1e30f, mx1 = -1e30f;
#pragma unroll
        for (int nf = 0; nf < 8; nf++) {
            mx0 = fmaxf(mx0, fmaxf(sc[nf][0], sc[nf][1]));
            mx1 = fmaxf(mx1, fmaxf(sc[nf][2], sc[nf][3]));
        }
        mx0 = fmaxf(mx0, __shfl_xor_sync(0xffffffffu, mx0, 1));
        mx0 = fmaxf(mx0, __shfl_xor_sync(0xffffffffu, mx0, 2));
        mx1 = fmaxf(mx1, __shfl_xor_sync(0xffffffffu, mx1, 1));
        mx1 = fmaxf(mx1, __shfl_xor_sync(0xffffffffu, mx1, 2));

        float mn0 = fmaxf(m0, mx0), mn1 = fmaxf(m1, mx1);
        float a0 = fexp2(m0 - mn0), a1 = fexp2(m1 - mn1);
        float s0 = 0.f, s1 = 0.f;

#pragma unroll
        for (int nf = 0; nf < 8; nf++) {
            float p00 = fexp2(sc[nf][0] - mn0);
            float p01 = fexp2(sc[nf][1] - mn0);
            float p10 = fexp2(sc[nf][2] - mn1);
            float p11 = fexp2(sc[nf][3] - mn1);
            s0 += p00 + p01;
            s1 += p10 + p11;
            int c0 = nf * 8 + tig * 2;
            *(uint2*)&P_[(mb+gid)  *68 + c0] = make_uint2(f2tf(p00), f2tf(p01));
            *(uint2*)&P_[(mb+gid+8)*68 + c0] = make_uint2(f2tf(p10), f2tf(p11));
        }
        s0 += __shfl_xor_sync(0xffffffffu, s0, 1);
        s0 += __shfl_xor_sync(0xffffffffu, s0, 2);
        s1 += __shfl_xor_sync(0xffffffffu, s1, 1);
        s1 += __shfl_xor_sync(0xffffffffu, s1, 2);

        l0 = l0 * a0 + s0;
        l1 = l1 * a1 + s1;
        m0 = mn0; m1 = mn1;
#pragma unroll
        for (int nf = 0; nf < 8; nf++) {
            o[nf][0] *= a0; o[nf][1] *= a0;
            o[nf][2] *= a1; o[nf][3] *= a1;
        }
        __syncwarp();

        // O += P V (single tf32)
#pragma unroll
        for (int k8 = 0; k8 < 64; k8 += 8) {
            unsigned ap[4];
            ap[0] = P_[(mb+gid)  *68 + k8+tig];
            ap[1] = P_[(mb+gid+8)*68 + k8+tig];
            ap[2] = P_[(mb+gid)  *68 + k8+tig+4];
            ap[3] = P_[(mb+gid+8)*68 + k8+tig+4];
#pragma unroll
            for (int nf = 0; nf < 8; nf++) {
                unsigned bv[2];
                bv[0] = V_[(k8+tig)  *72 + nf*8+gid];
                bv[1] = V_[(k8+tig+4)*72 + nf*8+gid];
                mma8(o[nf], ap, bv);
            }
        }
        __syncthreads();
    }

    // epilogue: normalize, bf16 hi/lo split, scatter to [B,S,D]
    float il0 = 1.f / l0, il1 = 1.f / l1;
    int b = bh >> 4, h = bh & 15;
#pragma unroll
    for (int nf = 0; nf < 8; nf++) {
        int dh = nf * 8 + tig * 2;
        size_t d0 = ((size_t)(b * S_LEN + rowg0)) * DMODEL + h * 64 + dh;
        size_t d1 = ((size_t)(b * S_LEN + rowg1)) * DMODEL + h * 64 + dh;
        float v;
        v = o[nf][0] * il0; { __nv_bfloat16 hh = __float2bfloat16(v); g_OHb[d0]   = hh; g_OLb[d0]   = __float2bfloat16(v - __bfloat162float(hh)); }
        v = o[nf][1] * il0; { __nv_bfloat16 hh = __float2bfloat16(v); g_OHb[d0+1] = hh; g_OLb[d0+1] = __float2bfloat16(v - __bfloat162float(hh)); }
        v = o[nf][2] * il1; { __nv_bfloat16 hh = __float2bfloat16(v); g_OHb[d1]   = hh; g_OLb[d1]   = __float2bfloat16(v - __bfloat162float(hh)); }
        v = o[nf][3] * il1; { __nv_bfloat16 hh = __float2bfloat16(v); g_OHb[d1+1] = hh; g_OLb[d1+1] = __float2bfloat16(v - __bfloat162float(hh)); }
    }
}

// ---------------- launch ----------------
extern "C" void kernel_launch(void* const* d_in, const int* in_sizes, int n_in,
                              void* d_out, int out_size) {
    (void)in_sizes; (void)n_in; (void)out_size;
    const float* x  = (const float*)d_in[0];
    const float* Wq = (const float*)d_in[1];
    const float* Wk = (const float*)d_in[2];
    const float* Wv = (const float*)d_in[3];
    const float* Wo = (const float*)d_in[4];
    float* out = (float*)d_out;

    __nv_bfloat16 *XHb, *XLb, *WTH, *WTL, *QHb, *QLb, *KHb, *KLb, *OHb, *OLb;
    float *V;
    cudaGetSymbolAddress((void**)&XHb, g_XHb);
    cudaGetSymbolAddress((void**)&XLb, g_XLb);
    cudaGetSymbolAddress((void**)&WTH, g_WTH);
    cudaGetSymbolAddress((void**)&WTL, g_WTL);
    cudaGetSymbolAddress((void**)&QHb, g_QHb);
    cudaGetSymbolAddress((void**)&QLb, g_QLb);
    cudaGetSymbolAddress((void**)&KHb, g_KHb);
    cudaGetSymbolAddress((void**)&KLb, g_KLb);
    cudaGetSymbolAddress((void**)&OHb, g_OHb);
    cudaGetSymbolAddress((void**)&OLb, g_OLb);
    cudaGetSymbolAddress((void**)&V,  g_V);

    cudaFuncSetAttribute(gemm_bf<0>, cudaFuncAttributeMaxDynamicSharedMemorySize, G_SMEM);
    cudaFuncSetAttribute(gemm_bf<1>, cudaFuncAttributeMaxDynamicSharedMemorySize, G_SMEM);
    cudaFuncSetAttribute(gemm_bf<2>, cudaFuncAttributeMaxDynamicSharedMemorySize, G_SMEM);
    cudaFuncSetAttribute(gemm_bf<3>, cudaFuncAttributeMaxDynamicSharedMemorySize, G_SMEM);
    cudaFuncSetAttribute(attn2_kernel, cudaFuncAttributeMaxDynamicSharedMemorySize, AT_SMEM);

    rope_init_kernel<<<(S_LEN * 32 + 255) / 256, 256>>>();

    const int NX4 = MTOK * DMODEL / 4;
    xsplit_kernel<<<(NX4 + 255) / 256, 256>>>((const float4*)x, XHb, XLb, NX4);

    const size_t WSTEP = (size_t)DMODEL * DMODEL;
    dim3 tgrid(32, 32), tblk(32, 8);
    wtrans_kernel<<<tgrid, tblk>>>(Wq, WTH + 0*WSTEP, WTL + 0*WSTEP);
    wtrans_kernel<<<tgrid, tblk>>>(Wk, WTH + 1*WSTEP, WTL + 1*WSTEP);
    wtrans_kernel<<<tgrid, tblk>>>(Wv, WTH + 2*WSTEP, WTL + 2*WSTEP);
    wtrans_kernel<<<tgrid, tblk>>>(Wo, WTH + 3*WSTEP, WTL + 3*WSTEP);

    dim3 ggrid(DMODEL / 128, MTOK / 128);
    gemm_bf<1><<<ggrid, 256, G_SMEM>>>(XHb, XLb, WTH + 0*WSTEP, WTL + 0*WSTEP, QHb, QLb);
    gemm_bf<2><<<ggrid, 256, G_SMEM>>>(XHb, XLb, WTH + 1*WSTEP, WTL + 1*WSTEP, KHb, KLb);
    gemm_bf<3><<<ggrid, 256, G_SMEM>>>(XHb, XLb, WTH + 2*WSTEP, WTL + 2*WSTEP, V, nullptr);

    attn2_kernel<<<dim3(S_LEN / 128, BATCH * NHEAD), 256, AT_SMEM>>>();

    gemm_bf<0><<<ggrid, 256, G_SMEM>>>(OHb, OLb, WTH + 3*WSTEP, WTL + 3*WSTEP, out, nullptr);
}

// round 7
// speedup vs baseline: 3.2364x; 1.3345x over previous
#include <cuda_runtime.h>
#include <cuda_fp16.h>
#include <math.h>

#define S_LEN   2048
#define BATCH   4
#define NHEAD   16
#define DK      64
#define DMODEL  1024
#define MTOK    (BATCH*S_LEN)   // 8192
#define QSCALE  0.18033688011112043f   // log2(e)/8
#define WSC     8.0f                   // W pre-scale (keeps W_lo normal in fp16)
#define WUNSC   0.125f

// ---------------- scratch ----------------
__device__ __half g_Xh [(size_t)MTOK*DMODEL];
__device__ __half g_WTH[(size_t)4*DMODEL*DMODEL];   // 8*W transposed [N,K], fp16 hi
__device__ __half g_WTL[(size_t)4*DMODEL*DMODEL];   // fp16 lo
__device__ __half g_Qh [(size_t)MTOK*DMODEL];       // QSCALE applied
__device__ __half g_KH [(size_t)MTOK*DMODEL];
__device__ __half g_KL [(size_t)MTOK*DMODEL];
__device__ __half g_Oh [(size_t)MTOK*DMODEL];
__device__ float  g_V  [(size_t)MTOK*DMODEL];
__device__ float  g_rc [S_LEN*32];
__device__ float  g_rs [S_LEN*32];

// ---------------- helpers ----------------
__device__ __forceinline__ unsigned f2tf(float x) {
    unsigned r;
    asm("cvt.rna.tf32.f32 %0, %1;" : "=r"(r) : "f"(x));
    return r;
}
// tf32 m16n8k8 (PV path)
__device__ __forceinline__ void mma8(float* c, const unsigned* a, const unsigned* b) {
    asm volatile(
        "mma.sync.aligned.m16n8k8.row.col.f32.tf32.tf32.f32 "
        "{%0,%1,%2,%3},{%4,%5,%6,%7},{%8,%9},{%0,%1,%2,%3};\n"
        : "+f"(c[0]), "+f"(c[1]), "+f"(c[2]), "+f"(c[3])
        : "r"(a[0]), "r"(a[1]), "r"(a[2]), "r"(a[3]), "r"(b[0]), "r"(b[1]));
}
// fp16 m16n8k16 (GEMM + scores): each 32-bit reg = fp16 k-pair
__device__ __forceinline__ void mma16f(float* c, const unsigned* a, const unsigned* b) {
    asm volatile(
        "mma.sync.aligned.m16n8k16.row.col.f32.f16.f16.f32 "
        "{%0,%1,%2,%3},{%4,%5,%6,%7},{%8,%9},{%0,%1,%2,%3};\n"
        : "+f"(c[0]), "+f"(c[1]), "+f"(c[2]), "+f"(c[3])
        : "r"(a[0]), "r"(a[1]), "r"(a[2]), "r"(a[3]), "r"(b[0]), "r"(b[1]));
}
__device__ __forceinline__ unsigned s2u(const void* p) {
    unsigned a;
    asm("{ .reg .u64 t; cvta.to.shared.u64 t, %1; cvt.u32.u64 %0, t; }" : "=r"(a) : "l"(p));
    return a;
}
#define CPA(d, s)  asm volatile("cp.async.cg.shared.global [%0], [%1], 16;\n" :: "r"(d), "l"(s))
#define CPCOMMIT() asm volatile("cp.async.commit_group;\n")
#define CPWAIT0()  asm volatile("cp.async.wait_group 0;\n")
#define CPWAIT1()  asm volatile("cp.async.wait_group 1;\n")

// fast 2^x on fma/alu pipes (no MUFU)
__device__ __forceinline__ float fexp2(float d) {
    d = fmaxf(d, -120.f);
    float r = d + 12582912.f;
    int ib = __float_as_int(r);
    float f = d - (r - 12582912.f);
    float p = 1.f + f*(0.69314718056f + f*(0.240226506959f + f*(0.0555041086648f +
              f*(0.00961812910763f + f*0.00133335581464f))));
    return __int_as_float(__float_as_int(p) + (ib << 23));
}

// ---------------- RoPE table ----------------
__global__ void rope_init_kernel() {
    int i = blockIdx.x * blockDim.x + threadIdx.x;
    if (i >= S_LEN * 32) return;
    int s = i >> 5, j = i & 31;
    double invf = pow(10000.0, -((double)(2*j)) / (double)DK);
    double a = (double)s * invf;
    g_rc[i] = (float)cos(a);
    g_rs[i] = (float)sin(a);
}

// ---------------- x -> fp16 ----------------
__global__ void xh_kernel(const float4* __restrict__ X, __half* __restrict__ H, int n4) {
    int i = blockIdx.x * blockDim.x + threadIdx.x;
    if (i >= n4) return;
    float4 v = X[i];
    __half2* Hp = (__half2*)(H + (size_t)i * 4);
    Hp[0] = __half2(__float2half(v.x), __float2half(v.y));
    Hp[1] = __half2(__float2half(v.z), __float2half(v.w));
}

// ---------------- W[K,N] -> 8*W^T[N,K] fp16 hi/lo ----------------
__global__ void wtrans_kernel(const float* __restrict__ W, __half* __restrict__ TH,
                              __half* __restrict__ TL) {
    __shared__ float t[32][33];
    int n0 = blockIdx.x * 32, k0 = blockIdx.y * 32;
    int tx = threadIdx.x, ty = threadIdx.y;
#pragma unroll
    for (int j = 0; j < 32; j += 8)
        t[ty + j][tx] = W[(size_t)(k0 + ty + j) * DMODEL + n0 + tx];
    __syncthreads();
#pragma unroll
    for (int j = 0; j < 32; j += 8) {
        float v = t[tx][ty + j] * WSC;
        int n = n0 + ty + j, k = k0 + tx;
        __half hv = __float2half(v);
        TH[(size_t)n * DMODEL + k] = hv;
        TL[(size_t)n * DMODEL + k] = __float2half(v - __half2float(hv));
    }
}

// ---------------- 2xFP16 GEMM: C = A[M,K](fp16) * (8W)^T hi/lo, *0.125 in epilogue ----------------
// MODE 0: fp32 store. MODE 1: Q rope+QSCALE -> fp16 scatter. MODE 2: K rope -> fp16 hi/lo scatter.
// MODE 3: V -> tf32 fp32 scatter.
#define GS 20
#define GW_A  0
#define GW_BH 2560
#define GW_BL 5120
#define GW_STG 7680
#define G_SMEM (2*GW_STG*4)   // 61440 bytes -> 2 CTAs/SM

template<int MODE>
__global__ void __launch_bounds__(256, 2) gemm_fp(const __half* __restrict__ A,
                                                  const __half* __restrict__ BH,
                                                  const __half* __restrict__ BL,
                                                  void* __restrict__ C0v,
                                                  void* __restrict__ C1v) {
    extern __shared__ unsigned sm[];
    const int tid = threadIdx.x, lane = tid & 31, warp = tid >> 5;
    const int wm = warp >> 1, wn = warp & 1, gid = lane >> 2, tig = lane & 3;
    const int bm = blockIdx.y * 128, bn = blockIdx.x * 128;
    unsigned sbase = s2u(sm);

    float acc[2][8][4];
#pragma unroll
    for (int mf = 0; mf < 2; mf++)
#pragma unroll
        for (int nf = 0; nf < 8; nf++)
#pragma unroll
            for (int c = 0; c < 4; c++) acc[mf][nf][c] = 0.f;

    auto load_stage = [&](int st, int k0) {
        unsigned stb = sbase + (unsigned)(st * GW_STG) * 4u;
#pragma unroll
        for (int i = 0; i < 2; i++) {
            int lin = tid + i * 256;                 // 0..511
            int row = lin >> 2, ck = lin & 3;        // 128 rows x 4 chunks (16B = 8 fp16)
            unsigned wo = (unsigned)(row * GS + ck * 4) * 4u;
            CPA(stb + GW_A*4u  + wo, A  + (size_t)(bm + row) * DMODEL + k0 + ck * 8);
            CPA(stb + GW_BH*4u + wo, BH + (size_t)(bn + row) * DMODEL + k0 + ck * 8);
            CPA(stb + GW_BL*4u + wo, BL + (size_t)(bn + row) * DMODEL + k0 + ck * 8);
        }
    };

    load_stage(0, 0);
    CPCOMMIT();
    for (int kt = 0; kt < 32; kt++) {
        if (kt + 1 < 32) {
            load_stage((kt + 1) & 1, (kt + 1) * 32);
            CPCOMMIT();
            CPWAIT1();
        } else {
            CPWAIT0();
        }
        __syncthreads();

        unsigned* As  = sm + (kt & 1) * GW_STG;
        unsigned* Bs  = As + GW_BH;
        unsigned* Blo = As + GW_BL;

#pragma unroll
        for (int ks = 0; ks < 2; ks++) {
            unsigned ah[2][4];
#pragma unroll
            for (int mf = 0; mf < 2; mf++) {
                int mr = wm * 32 + mf * 16;
                ah[mf][0] = As[(mr+gid)  *GS + ks*8 + tig];
                ah[mf][1] = As[(mr+gid+8)*GS + ks*8 + tig];
                ah[mf][2] = As[(mr+gid)  *GS + ks*8 + tig+4];
                ah[mf][3] = As[(mr+gid+8)*GS + ks*8 + tig+4];
            }
#pragma unroll
            for (int nf = 0; nf < 8; nf++) {
                int nc = wn * 64 + nf * 8;
                unsigned bh2[2], bl2[2];
                bh2[0] = Bs [(nc+gid)*GS + ks*8 + tig];
                bh2[1] = Bs [(nc+gid)*GS + ks*8 + tig+4];
                bl2[0] = Blo[(nc+gid)*GS + ks*8 + tig];
                bl2[1] = Blo[(nc+gid)*GS + ks*8 + tig+4];
#pragma unroll
                for (int mf = 0; mf < 2; mf++) {
                    mma16f(acc[mf][nf], ah[mf], bh2);
                    mma16f(acc[mf][nf], ah[mf], bl2);
                }
            }
        }
        __syncthreads();
    }

    // epilogue (undo WSC)
    float* C0f = (float*)C0v;
    __half* C0h = (__half*)C0v;
    __half* C1h = (__half*)C1v;
#pragma unroll
    for (int mf = 0; mf < 2; mf++) {
#pragma unroll
        for (int nf = 0; nf < 8; nf++) {
            int r0 = bm + wm * 32 + mf * 16 + gid;
            int nc = bn + wn * 64 + nf * 8 + tig * 2;
            if (MODE == 0) {
                C0f[(size_t)r0 * DMODEL + nc]           = acc[mf][nf][0] * WUNSC;
                C0f[(size_t)r0 * DMODEL + nc + 1]       = acc[mf][nf][1] * WUNSC;
                C0f[(size_t)(r0 + 8) * DMODEL + nc]     = acc[mf][nf][2] * WUNSC;
                C0f[(size_t)(r0 + 8) * DMODEL + nc + 1] = acc[mf][nf][3] * WUNSC;
            } else {
#pragma unroll
                for (int rr = 0; rr < 2; rr++) {
                    int r = r0 + rr * 8;
                    float v0 = acc[mf][nf][rr * 2];
                    float v1 = acc[mf][nf][rr * 2 + 1];
                    int b = r >> 11, s = r & (S_LEN - 1);
                    int h = nc >> 6, dh = nc & 63;
                    if (MODE == 1 || MODE == 2) {
                        int j = dh >> 1;
                        float cs = g_rc[s * 32 + j], sn = g_rs[s * 32 + j];
                        float t0 = v0 * cs - v1 * sn;
                        float t1 = v1 * cs + v0 * sn;
                        v0 = t0; v1 = t1;
                    }
                    size_t dst = ((size_t)(b * NHEAD + h) * S_LEN + s) * DK + dh;
                    if (MODE == 1) {
                        v0 *= WUNSC * QSCALE; v1 *= WUNSC * QSCALE;
                        *(__half2*)(C0h + dst) = __half2(__float2half(v0), __float2half(v1));
                    } else if (MODE == 2) {
                        v0 *= WUNSC; v1 *= WUNSC;
                        __half h0 = __float2half(v0);
                        __half h1 = __float2half(v1);
                        *(__half2*)(C0h + dst) = __half2(h0, h1);
                        *(__half2*)(C1h + dst) = __half2(__float2half(v0 - __half2float(h0)),
                                                         __float2half(v1 - __half2float(h1)));
                    } else { // MODE 3: V
                        C0f[dst]     = __uint_as_float(f2tf(v0 * WUNSC));
                        C0f[dst + 1] = __uint_as_float(f2tf(v1 * WUNSC));
                    }
                }
            }
        }
    }
}

// ---------------- flash attention: Br=128, Bc=64; fp16 2-term scores + tf32 PV ----------------
#define AT_Q  0                       // 128 x 36 (fp16 pairs)
#define AT_P  4608                    // 128 x 68 tf32
#define AT_KH 13312                   // 2 stages x (64 x 36)
#define AT_KL 17920
#define AT_V  22528                   // 2 stages x (64 x 72) fp32
#define AT_WORDS 31744
#define AT_SMEM (AT_WORDS*4)          // 126976 bytes

__global__ void __launch_bounds__(256) attn2_kernel() {
    extern __shared__ unsigned sm[];
    const int tid = threadIdx.x, lane = tid & 31, warp = tid >> 5;
    const int gid = lane >> 2, tig = lane & 3;
    const int qt = (gridDim.x - 1) - blockIdx.x;
    const int bh = blockIdx.y;
    const int mb = warp * 16;
    unsigned sbase = s2u(sm);

    const __half* Qg  = g_Qh + (size_t)bh * S_LEN * DK + (size_t)qt * 128 * DK;
    const __half* KHg = g_KH + (size_t)bh * S_LEN * DK;
    const __half* KLg = g_KL + (size_t)bh * S_LEN * DK;
    const float*  Vg  = g_V  + (size_t)bh * S_LEN * DK;

    // Q tile: 128 rows x 8 chunks(16B)
#pragma unroll
    for (int i = 0; i < 4; i++) {
        int lin = tid + i * 256;
        int row = lin >> 3, ck = lin & 7;
        CPA(sbase + AT_Q*4u + (unsigned)(row * 36 + ck * 4) * 4u, Qg + row * 64 + ck * 8);
    }

    auto load_kv = [&](int st, int kt) {
        size_t off = (size_t)kt * 64 * DK;
#pragma unroll
        for (int i = 0; i < 2; i++) {
            int lin = tid + i * 256;
            int row = lin >> 3, ck = lin & 7;
            unsigned wo = (unsigned)(row * 36 + ck * 4) * 4u;
            CPA(sbase + (AT_KH + st*2304)*4u + wo, KHg + off + row * 64 + ck * 8);
            CPA(sbase + (AT_KL + st*2304)*4u + wo, KLg + off + row * 64 + ck * 8);
        }
#pragma unroll
        for (int i = 0; i < 4; i++) {
            int lin = tid + i * 256;
            int row = lin >> 4, c4 = (lin & 15) << 2;
            CPA(sbase + (AT_V + st*4608)*4u + (unsigned)(row * 72 + c4) * 4u,
                Vg + off + row * 64 + c4);
        }
    };

    const int rowg0 = qt * 128 + mb + gid;
    const int rowg1 = rowg0 + 8;
    float m0 = -1e30f, m1 = -1e30f, l0 = 0.f, l1 = 0.f;
    float o[8][4];
#pragma unroll
    for (int nf = 0; nf < 8; nf++)
#pragma unroll
        for (int c = 0; c < 4; c++) o[nf][c] = 0.f;

    const int kmax = 2 * qt + 2;
    load_kv(0, 0);
    CPCOMMIT();

    for (int kt = 0; kt < kmax; kt++) {
        if (kt + 1 < kmax) load_kv((kt + 1) & 1, kt + 1);
        CPCOMMIT();
        CPWAIT1();
        __syncthreads();

        unsigned* Q_  = sm + AT_Q;
        unsigned* P_  = sm + AT_P;
        unsigned* KH_ = sm + AT_KH + (kt & 1) * 2304;
        unsigned* KL_ = sm + AT_KL + (kt & 1) * 2304;
        unsigned* V_  = sm + AT_V  + (kt & 1) * 4608;

        // S = Q K^T (fp16 2-term)
        float sc[8][4];
#pragma unroll
        for (int nf = 0; nf < 8; nf++)
#pragma unroll
            for (int c = 0; c < 4; c++) sc[nf][c] = 0.f;

#pragma unroll
        for (int ks = 0; ks < 4; ks++) {
            unsigned ah[4];
            ah[0] = Q_[(mb+gid)  *36 + ks*8 + tig];
            ah[1] = Q_[(mb+gid+8)*36 + ks*8 + tig];
            ah[2] = Q_[(mb+gid)  *36 + ks*8 + tig+4];
            ah[3] = Q_[(mb+gid+8)*36 + ks*8 + tig+4];
#pragma unroll
            for (int nf = 0; nf < 8; nf++) {
                unsigned bh2[2], bl2[2];
                bh2[0] = KH_[(nf*8+gid)*36 + ks*8 + tig];
                bh2[1] = KH_[(nf*8+gid)*36 + ks*8 + tig+4];
                bl2[0] = KL_[(nf*8+gid)*36 + ks*8 + tig];
                bl2[1] = KL_[(nf*8+gid)*36 + ks*8 + tig+4];
                mma16f(sc[nf], ah, bh2);
                mma16f(sc[nf], ah, bl2);
            }
        }

        if (kt >= 2 * qt) {    // diagonal tiles
#pragma unroll
            for (int nf = 0; nf < 8; nf++) {
                int cg = kt * 64 + nf * 8 + tig * 2;
                if (cg     > rowg0) sc[nf][0] = -1e30f;
                if (cg + 1 > rowg0) sc[nf][1] = -1e30f;
                if (cg     > rowg1) sc[nf][2] = -1e30f;
                if (cg + 1 > rowg1) sc[nf][3] = -1e30f;
            }
        }

        // online softmax (base-2)
        float mx0 = -1e30f, mx1 = -1e30f;
#pragma unroll
        for (int nf = 0; nf < 8; nf++) {
            mx0 = fmaxf(mx0, fmaxf(sc[nf][0], sc[nf][1]));
            mx1 = fmaxf(mx1, fmaxf(sc[nf][2], sc[nf][3]));
        }
        mx0 = fmaxf(mx0, __shfl_xor_sync(0xffffffffu, mx0, 1));
        mx0 = fmaxf(mx0, __shfl_xor_sync(0xffffffffu, mx0, 2));
        mx1 = fmaxf(mx1, __shfl_xor_sync(0xffffffffu, mx1, 1));
        mx1 = fmaxf(mx1, __shfl_xor_sync(0xffffffffu, mx1, 2));

        float mn0 = fmaxf(m0, mx0), mn1 = fmaxf(m1, mx1);
        float a0 = fexp2(m0 - mn0), a1 = fexp2(m1 - mn1);
        float s0 = 0.f, s1 = 0.f;

#pragma unroll
        for (int nf = 0; nf < 8; nf++) {
            float p00 = fexp2(sc[nf][0] - mn0);
            float p01 = fexp2(sc[nf][1] - mn0);
            float p10 = fexp2(sc[nf][2] - mn1);
            float p11 = fexp2(sc[nf][3] - mn1);
            s0 += p00 + p01;
            s1 += p10 + p11;
            int c0 = nf * 8 + tig * 2;
            *(uint2*)&P_[(mb+gid)  *68 + c0] = make_uint2(f2tf(p00), f2tf(p01));
            *(uint2*)&P_[(mb+gid+8)*68 + c0] = make_uint2(f2tf(p10), f2tf(p11));
        }
        s0 += __shfl_xor_sync(0xffffffffu, s0, 1);
        s0 += __shfl_xor_sync(0xffffffffu, s0, 2);
        s1 += __shfl_xor_sync(0xffffffffu, s1, 1);
        s1 += __shfl_xor_sync(0xffffffffu, s1, 2);

        l0 = l0 * a0 + s0;
        l1 = l1 * a1 + s1;
        m0 = mn0; m1 = mn1;
#pragma unroll
        for (int nf = 0; nf < 8; nf++) {
            o[nf][0] *= a0; o[nf][1] *= a0;
            o[nf][2] *= a1; o[nf][3] *= a1;
        }
        __syncwarp();

        // O += P V (single tf32)
#pragma unroll
        for (int k8 = 0; k8 < 64; k8 += 8) {
            unsigned ap[4];
            ap[0] = P_[(mb+gid)  *68 + k8+tig];
            ap[1] = P_[(mb+gid+8)*68 + k8+tig];
            ap[2] = P_[(mb+gid)  *68 + k8+tig+4];
            ap[3] = P_[(mb+gid+8)*68 + k8+tig+4];
#pragma unroll
            for (int nf = 0; nf < 8; nf++) {
                unsigned bv[2];
                bv[0] = V_[(k8+tig)  *72 + nf*8+gid];
                bv[1] = V_[(k8+tig+4)*72 + nf*8+gid];
                mma8(o[nf], ap, bv);
            }
        }
        __syncthreads();
    }

    // epilogue: normalize -> fp16, scatter to [B,S,D]
    float il0 = 1.f / l0, il1 = 1.f / l1;
    int b = bh >> 4, h = bh & 15;
#pragma unroll
    for (int nf = 0; nf < 8; nf++) {
        int dh = nf * 8 + tig * 2;
        size_t d0 = ((size_t)(b * S_LEN + rowg0)) * DMODEL + h * 64 + dh;
        size_t d1 = ((size_t)(b * S_LEN + rowg1)) * DMODEL + h * 64 + dh;
        *(__half2*)(g_Oh + d0) = __half2(__float2half(o[nf][0] * il0), __float2half(o[nf][1] * il0));
        *(__half2*)(g_Oh + d1) = __half2(__float2half(o[nf][2] * il1), __float2half(o[nf][3] * il1));
    }
}

// ---------------- launch ----------------
extern "C" void kernel_launch(void* const* d_in, const int* in_sizes, int n_in,
                              void* d_out, int out_size) {
    (void)in_sizes; (void)n_in; (void)out_size;
    const float* x  = (const float*)d_in[0];
    const float* Wq = (const float*)d_in[1];
    const float* Wk = (const float*)d_in[2];
    const float* Wv = (const float*)d_in[3];
    const float* Wo = (const float*)d_in[4];
    float* out = (float*)d_out;

    __half *Xh, *WTH, *WTL, *Qh, *KH, *KL, *Oh;
    float *V;
    cudaGetSymbolAddress((void**)&Xh,  g_Xh);
    cudaGetSymbolAddress((void**)&WTH, g_WTH);
    cudaGetSymbolAddress((void**)&WTL, g_WTL);
    cudaGetSymbolAddress((void**)&Qh,  g_Qh);
    cudaGetSymbolAddress((void**)&KH,  g_KH);
    cudaGetSymbolAddress((void**)&KL,  g_KL);
    cudaGetSymbolAddress((void**)&Oh,  g_Oh);
    cudaGetSymbolAddress((void**)&V,   g_V);

    cudaFuncSetAttribute(gemm_fp<0>, cudaFuncAttributeMaxDynamicSharedMemorySize, G_SMEM);
    cudaFuncSetAttribute(gemm_fp<1>, cudaFuncAttributeMaxDynamicSharedMemorySize, G_SMEM);
    cudaFuncSetAttribute(gemm_fp<2>, cudaFuncAttributeMaxDynamicSharedMemorySize, G_SMEM);
    cudaFuncSetAttribute(gemm_fp<3>, cudaFuncAttributeMaxDynamicSharedMemorySize, G_SMEM);
    cudaFuncSetAttribute(attn2_kernel, cudaFuncAttributeMaxDynamicSharedMemorySize, AT_SMEM);

    rope_init_kernel<<<(S_LEN * 32 + 255) / 256, 256>>>();

    const int NX4 = MTOK * DMODEL / 4;
    xh_kernel<<<(NX4 + 255) / 256, 256>>>((const float4*)x, Xh, NX4);

    const size_t WSTEP = (size_t)DMODEL * DMODEL;
    dim3 tgrid(32, 32), tblk(32, 8);
    wtrans_kernel<<<tgrid, tblk>>>(Wq, WTH + 0*WSTEP, WTL + 0*WSTEP);
    wtrans_kernel<<<tgrid, tblk>>>(Wk, WTH + 1*WSTEP, WTL + 1*WSTEP);
    wtrans_kernel<<<tgrid, tblk>>>(Wv, WTH + 2*WSTEP, WTL + 2*WSTEP);
    wtrans_kernel<<<tgrid, tblk>>>(Wo, WTH + 3*WSTEP, WTL + 3*WSTEP);

    dim3 ggrid(DMODEL / 128, MTOK / 128);
    gemm_fp<1><<<ggrid, 256, G_SMEM>>>(Xh, WTH + 0*WSTEP, WTL + 0*WSTEP, Qh, nullptr);
    gemm_fp<2><<<ggrid, 256, G_SMEM>>>(Xh, WTH + 1*WSTEP, WTL + 1*WSTEP, KH, KL);
    gemm_fp<3><<<ggrid, 256, G_SMEM>>>(Xh, WTH + 2*WSTEP, WTL + 2*WSTEP, V, nullptr);

    attn2_kernel<<<dim3(S_LEN / 128, BATCH * NHEAD), 256, AT_SMEM>>>();

    gemm_fp<0><<<ggrid, 256, G_SMEM>>>(Oh, WTH + 3*WSTEP, WTL + 3*WSTEP, out, nullptr);
}

// round 8
// speedup vs baseline: 3.8796x; 1.1987x over previous
#include <cuda_runtime.h>
#include <cuda_fp16.h>
#include <math.h>

#define S_LEN   2048
#define BATCH   4
#define NHEAD   16
#define DK      64
#define DMODEL  1024
#define MTOK    (BATCH*S_LEN)   // 8192
#define QSCALE  0.18033688011112043f   // log2(e)/8
#define WSC     8.0f
#define WUNSC   0.125f

// ---------------- scratch ----------------
__device__ __half g_Xh [(size_t)MTOK*DMODEL];
__device__ __half g_WTH[(size_t)4*DMODEL*DMODEL];   // 8*W^T [N,K] fp16 hi
__device__ __half g_WTL[(size_t)4*DMODEL*DMODEL];   // fp16 lo
__device__ __half g_Qh [(size_t)MTOK*DMODEL];       // [B,H,S,dk], QSCALE applied
__device__ __half g_KH [(size_t)MTOK*DMODEL];       // [B,H,S,dk]
__device__ __half g_KL [(size_t)MTOK*DMODEL];
__device__ __half g_Vh [(size_t)MTOK*DMODEL];       // TRANSPOSED [B,H,dk,S]
__device__ __half g_Oh [(size_t)MTOK*DMODEL];       // [B,S,D]
__device__ float  g_rc [S_LEN*32];
__device__ float  g_rs [S_LEN*32];

// ---------------- helpers ----------------
__device__ __forceinline__ void mma16f(float* c, const unsigned* a, const unsigned* b) {
    asm volatile(
        "mma.sync.aligned.m16n8k16.row.col.f32.f16.f16.f32 "
        "{%0,%1,%2,%3},{%4,%5,%6,%7},{%8,%9},{%0,%1,%2,%3};\n"
        : "+f"(c[0]), "+f"(c[1]), "+f"(c[2]), "+f"(c[3])
        : "r"(a[0]), "r"(a[1]), "r"(a[2]), "r"(a[3]), "r"(b[0]), "r"(b[1]));
}
__device__ __forceinline__ unsigned s2u(const void* p) {
    unsigned a;
    asm("{ .reg .u64 t; cvta.to.shared.u64 t, %1; cvt.u32.u64 %0, t; }" : "=r"(a) : "l"(p));
    return a;
}
#define CPA(d, s)  asm volatile("cp.async.cg.shared.global [%0], [%1], 16;\n" :: "r"(d), "l"(s))
#define CPCOMMIT() asm volatile("cp.async.commit_group;\n")
#define CPWAIT0()  asm volatile("cp.async.wait_group 0;\n")
#define CPWAIT1()  asm volatile("cp.async.wait_group 1;\n")

// fast 2^x on fma/alu pipes (no MUFU)
__device__ __forceinline__ float fexp2(float d) {
    d = fmaxf(d, -120.f);
    float r = d + 12582912.f;
    int ib = __float_as_int(r);
    float f = d - (r - 12582912.f);
    float p = 1.f + f*(0.69314718056f + f*(0.240226506959f + f*(0.0555041086648f +
              f*(0.00961812910763f + f*0.00133335581464f))));
    return __int_as_float(__float_as_int(p) + (ib << 23));
}

// ---------------- RoPE table ----------------
__global__ void rope_init_kernel() {
    int i = blockIdx.x * blockDim.x + threadIdx.x;
    if (i >= S_LEN * 32) return;
    int s = i >> 5, j = i & 31;
    double invf = pow(10000.0, -((double)(2*j)) / (double)DK);
    double a = (double)s * invf;
    g_rc[i] = (float)cos(a);
    g_rs[i] = (float)sin(a);
}

// ---------------- x -> fp16 ----------------
__global__ void xh_kernel(const float4* __restrict__ X, __half* __restrict__ H, int n4) {
    int i = blockIdx.x * blockDim.x + threadIdx.x;
    if (i >= n4) return;
    float4 v = X[i];
    __half2* Hp = (__half2*)(H + (size_t)i * 4);
    Hp[0] = __half2(__float2half(v.x), __float2half(v.y));
    Hp[1] = __half2(__float2half(v.z), __float2half(v.w));
}

// ---------------- 4x W[K,N] -> 8*W^T[N,K] fp16 hi/lo (fused over z) ----------------
__global__ void wtrans_kernel(const float* __restrict__ W0, const float* __restrict__ W1,
                              const float* __restrict__ W2, const float* __restrict__ W3,
                              __half* __restrict__ TH, __half* __restrict__ TL) {
    __shared__ float t[32][33];
    int z = blockIdx.z;
    const float* W = (z == 0) ? W0 : (z == 1) ? W1 : (z == 2) ? W2 : W3;
    __half* THz = TH + (size_t)z * DMODEL * DMODEL;
    __half* TLz = TL + (size_t)z * DMODEL * DMODEL;
    int n0 = blockIdx.x * 32, k0 = blockIdx.y * 32;
    int tx = threadIdx.x, ty = threadIdx.y;
#pragma unroll
    for (int j = 0; j < 32; j += 8)
        t[ty + j][tx] = W[(size_t)(k0 + ty + j) * DMODEL + n0 + tx];
    __syncthreads();
#pragma unroll
    for (int j = 0; j < 32; j += 8) {
        float v = t[tx][ty + j] * WSC;
        int n = n0 + ty + j, k = k0 + tx;
        __half hv = __float2half(v);
        THz[(size_t)n * DMODEL + k] = hv;
        TLz[(size_t)n * DMODEL + k] = __float2half(v - __half2float(hv));
    }
}

// ---------------- shared GEMM mainloop: acc = A[M,K](fp16) * B_hi/lo[N,K]^T ----------------
#define GS 20
#define GW_A  0
#define GW_BH 2560
#define GW_BL 5120
#define GW_STG 7680
#define G_SMEM (2*GW_STG*4)   // 61440 bytes -> 2 CTAs/SM

__device__ __forceinline__ void gemm_main(const __half* __restrict__ A,
                                          const __half* __restrict__ BH,
                                          const __half* __restrict__ BL,
                                          unsigned* sm, unsigned sbase,
                                          int tid, int bm, int bn,
                                          int wm, int wn, int gid, int tig,
                                          float acc[2][8][4]) {
    auto load_stage = [&](int st, int k0) {
        unsigned stb = sbase + (unsigned)(st * GW_STG) * 4u;
#pragma unroll
        for (int i = 0; i < 2; i++) {
            int lin = tid + i * 256;
            int row = lin >> 2, ck = lin & 3;
            unsigned wo = (unsigned)(row * GS + ck * 4) * 4u;
            CPA(stb + GW_A*4u  + wo, A  + (size_t)(bm + row) * DMODEL + k0 + ck * 8);
            CPA(stb + GW_BH*4u + wo, BH + (size_t)(bn + row) * DMODEL + k0 + ck * 8);
            CPA(stb + GW_BL*4u + wo, BL + (size_t)(bn + row) * DMODEL + k0 + ck * 8);
        }
    };

    load_stage(0, 0);
    CPCOMMIT();
    for (int kt = 0; kt < 32; kt++) {
        if (kt + 1 < 32) {
            load_stage((kt + 1) & 1, (kt + 1) * 32);
            CPCOMMIT();
            CPWAIT1();
        } else {
            CPWAIT0();
        }
        __syncthreads();

        unsigned* As  = sm + (kt & 1) * GW_STG;
        unsigned* Bs  = As + GW_BH;
        unsigned* Blo = As + GW_BL;

#pragma unroll
        for (int ks = 0; ks < 2; ks++) {
            unsigned ah[2][4];
#pragma unroll
            for (int mf = 0; mf < 2; mf++) {
                int mr = wm * 32 + mf * 16;
                ah[mf][0] = As[(mr+gid)  *GS + ks*8 + tig];
                ah[mf][1] = As[(mr+gid+8)*GS + ks*8 + tig];
                ah[mf][2] = As[(mr+gid)  *GS + ks*8 + tig+4];
                ah[mf][3] = As[(mr+gid+8)*GS + ks*8 + tig+4];
            }
#pragma unroll
            for (int nf = 0; nf < 8; nf++) {
                int nc = wn * 64 + nf * 8;
                unsigned bh2[2], bl2[2];
                bh2[0] = Bs [(nc+gid)*GS + ks*8 + tig];
                bh2[1] = Bs [(nc+gid)*GS + ks*8 + tig+4];
                bl2[0] = Blo[(nc+gid)*GS + ks*8 + tig];
                bl2[1] = Blo[(nc+gid)*GS + ks*8 + tig+4];
#pragma unroll
                for (int mf = 0; mf < 2; mf++) {
                    mma16f(acc[mf][nf], ah[mf], bh2);
                    mma16f(acc[mf][nf], ah[mf], bl2);
                }
            }
        }
        __syncthreads();
    }
}

// ---------------- fused QKV GEMM (mode = blockIdx.z: 0=Q, 1=K, 2=V) ----------------
__global__ void __launch_bounds__(256, 2) gemm_qkv(const __half* __restrict__ A,
                                                   const __half* __restrict__ WTH,
                                                   const __half* __restrict__ WTL) {
    extern __shared__ unsigned sm[];
    const int tid = threadIdx.x, lane = tid & 31, warp = tid >> 5;
    const int wm = warp >> 1, wn = warp & 1, gid = lane >> 2, tig = lane & 3;
    const int bm = blockIdx.y * 128, bn = blockIdx.x * 128;
    const int mode = blockIdx.z;
    unsigned sbase = s2u(sm);

    const size_t WSTEP = (size_t)DMODEL * DMODEL;
    const __half* BH = WTH + (size_t)mode * WSTEP;
    const __half* BL = WTL + (size_t)mode * WSTEP;

    float acc[2][8][4];
#pragma unroll
    for (int mf = 0; mf < 2; mf++)
#pragma unroll
        for (int nf = 0; nf < 8; nf++)
#pragma unroll
            for (int c = 0; c < 4; c++) acc[mf][nf][c] = 0.f;

    gemm_main(A, BH, BL, sm, sbase, tid, bm, bn, wm, wn, gid, tig, acc);

#pragma unroll
    for (int mf = 0; mf < 2; mf++) {
#pragma unroll
        for (int nf = 0; nf < 8; nf++) {
            int r0 = bm + wm * 32 + mf * 16 + gid;
            int nc = bn + wn * 64 + nf * 8 + tig * 2;
#pragma unroll
            for (int rr = 0; rr < 2; rr++) {
                int r = r0 + rr * 8;
                float v0 = acc[mf][nf][rr * 2];
                float v1 = acc[mf][nf][rr * 2 + 1];
                int b = r >> 11, s = r & (S_LEN - 1);
                int h = nc >> 6, dh = nc & 63;
                if (mode != 2) {   // RoPE for Q,K
                    int j = dh >> 1;
                    float cs = g_rc[s * 32 + j], sn = g_rs[s * 32 + j];
                    float t0 = v0 * cs - v1 * sn;
                    float t1 = v1 * cs + v0 * sn;
                    v0 = t0; v1 = t1;
                }
                if (mode == 0) {
                    v0 *= WUNSC * QSCALE; v1 *= WUNSC * QSCALE;
                    size_t dst = ((size_t)(b * NHEAD + h) * S_LEN + s) * DK + dh;
                    *(__half2*)(g_Qh + dst) = __half2(__float2half(v0), __float2half(v1));
                } else if (mode == 1) {
                    v0 *= WUNSC; v1 *= WUNSC;
                    size_t dst = ((size_t)(b * NHEAD + h) * S_LEN + s) * DK + dh;
                    __half h0 = __float2half(v0);
                    __half h1 = __float2half(v1);
                    *(__half2*)(g_KH + dst) = __half2(h0, h1);
                    *(__half2*)(g_KL + dst) = __half2(__float2half(v0 - __half2float(h0)),
                                                      __float2half(v1 - __half2float(h1)));
                } else {           // V: transposed [B,H,dk,S]
                    size_t dstT = ((size_t)((b * NHEAD + h) * DK + dh)) * S_LEN + s;
                    g_Vh[dstT]         = __float2half(v0 * WUNSC);
                    g_Vh[dstT + S_LEN] = __float2half(v1 * WUNSC);
                }
            }
        }
    }
}

// ---------------- output projection GEMM (fp32 out) ----------------
__global__ void __launch_bounds__(256, 2) gemm_out(const __half* __restrict__ A,
                                                   const __half* __restrict__ BH,
                                                   const __half* __restrict__ BL,
                                                   float* __restrict__ C) {
    extern __shared__ unsigned sm[];
    const int tid = threadIdx.x, lane = tid & 31, warp = tid >> 5;
    const int wm = warp >> 1, wn = warp & 1, gid = lane >> 2, tig = lane & 3;
    const int bm = blockIdx.y * 128, bn = blockIdx.x * 128;
    unsigned sbase = s2u(sm);

    float acc[2][8][4];
#pragma unroll
    for (int mf = 0; mf < 2; mf++)
#pragma unroll
        for (int nf = 0; nf < 8; nf++)
#pragma unroll
            for (int c = 0; c < 4; c++) acc[mf][nf][c] = 0.f;

    gemm_main(A, BH, BL, sm, sbase, tid, bm, bn, wm, wn, gid, tig, acc);

#pragma unroll
    for (int mf = 0; mf < 2; mf++) {
#pragma unroll
        for (int nf = 0; nf < 8; nf++) {
            int r0 = bm + wm * 32 + mf * 16 + gid;
            int nc = bn + wn * 64 + nf * 8 + tig * 2;
            C[(size_t)r0 * DMODEL + nc]           = acc[mf][nf][0] * WUNSC;
            C[(size_t)r0 * DMODEL + nc + 1]       = acc[mf][nf][1] * WUNSC;
            C[(size_t)(r0 + 8) * DMODEL + nc]     = acc[mf][nf][2] * WUNSC;
            C[(size_t)(r0 + 8) * DMODEL + nc + 1] = acc[mf][nf][3] * WUNSC;
        }
    }
}

// ---------------- flash attention: Br=128, Bc=64; fp16 scores (2-term) + fp16 PV ----------------
// word offsets
#define AT_Q  0                       // 128 x 36 (fp16 pairs)
#define AT_P  4608                    // 128 x 36 (fp16 pairs)
#define AT_KH 9216                    // 2 stages x (64 x 36)
#define AT_KL 13824
#define AT_V  18432                   // 2 stages x (64 x 36)  V^T tile: [dh][kv]
#define AT_WORDS 23040
#define AT_SMEM (AT_WORDS*4)          // 92160 bytes -> 2 CTAs/SM

__global__ void __launch_bounds__(256) attn2_kernel() {
    extern __shared__ unsigned sm[];
    const int tid = threadIdx.x, lane = tid & 31, warp = tid >> 5;
    const int gid = lane >> 2, tig = lane & 3;
    const int qt = (gridDim.x - 1) - blockIdx.x;
    const int bh = blockIdx.y;
    const int mb = warp * 16;
    unsigned sbase = s2u(sm);

    const __half* Qg  = g_Qh + (size_t)bh * S_LEN * DK + (size_t)qt * 128 * DK;
    const __half* KHg = g_KH + (size_t)bh * S_LEN * DK;
    const __half* KLg = g_KL + (size_t)bh * S_LEN * DK;
    const __half* Vtg = g_Vh + (size_t)bh * S_LEN * DK;   // [dk][S]

    // Q tile: 128 rows x 8 chunks(16B)
#pragma unroll
    for (int i = 0; i < 4; i++) {
        int lin = tid + i * 256;
        int row = lin >> 3, ck = lin & 7;
        CPA(sbase + AT_Q*4u + (unsigned)(row * 36 + ck * 4) * 4u, Qg + row * 64 + ck * 8);
    }

    auto load_kv = [&](int st, int kt) {
        size_t koff = (size_t)kt * 64 * DK;
#pragma unroll
        for (int i = 0; i < 2; i++) {
            int lin = tid + i * 256;
            int row = lin >> 3, ck = lin & 7;
            unsigned wo = (unsigned)(row * 36 + ck * 4) * 4u;
            CPA(sbase + (AT_KH + st*2304)*4u + wo, KHg + koff + row * 64 + ck * 8);
            CPA(sbase + (AT_KL + st*2304)*4u + wo, KLg + koff + row * 64 + ck * 8);
        }
        // V^T tile: 64 dh-rows x 8 chunks of kv (contiguous in global)
#pragma unroll
        for (int i = 0; i < 2; i++) {
            int lin = tid + i * 256;
            int row = lin >> 3, ck = lin & 7;
            unsigned wo = (unsigned)(row * 36 + ck * 4) * 4u;
            CPA(sbase + (AT_V + st*2304)*4u + wo, Vtg + (size_t)row * S_LEN + kt * 64 + ck * 8);
        }
    };

    const int rowg0 = qt * 128 + mb + gid;
    const int rowg1 = rowg0 + 8;
    float m0 = -1e30f, m1 = -1e30f, l0 = 0.f, l1 = 0.f;
    float o[8][4];
#pragma unroll
    for (int nf = 0; nf < 8; nf++)
#pragma unroll
        for (int c = 0; c < 4; c++) o[nf][c] = 0.f;

    const int kmax = 2 * qt + 2;
    load_kv(0, 0);
    CPCOMMIT();

    for (int kt = 0; kt < kmax; kt++) {
        if (kt + 1 < kmax) load_kv((kt + 1) & 1, kt + 1);
        CPCOMMIT();
        CPWAIT1();
        __syncthreads();

        unsigned* Q_  = sm + AT_Q;
        unsigned* P_  = sm + AT_P;
        unsigned* KH_ = sm + AT_KH + (kt & 1) * 2304;
        unsigned* KL_ = sm + AT_KL + (kt & 1) * 2304;
        unsigned* V_  = sm + AT_V  + (kt & 1) * 2304;

        // S = Q K^T (fp16 2-term)
        float sc[8][4];
#pragma unroll
        for (int nf = 0; nf < 8; nf++)
#pragma unroll
            for (int c = 0; c < 4; c++) sc[nf][c] = 0.f;

#pragma unroll
        for (int ks = 0; ks < 4; ks++) {
            unsigned ah[4];
            ah[0] = Q_[(mb+gid)  *36 + ks*8 + tig];
            ah[1] = Q_[(mb+gid+8)*36 + ks*8 + tig];
            ah[2] = Q_[(mb+gid)  *36 + ks*8 + tig+4];
            ah[3] = Q_[(mb+gid+8)*36 + ks*8 + tig+4];
#pragma unroll
            for (int nf = 0; nf < 8; nf++) {
                unsigned bh2[2], bl2[2];
                bh2[0] = KH_[(nf*8+gid)*36 + ks*8 + tig];
                bh2[1] = KH_[(nf*8+gid)*36 + ks*8 + tig+4];
                bl2[0] = KL_[(nf*8+gid)*36 + ks*8 + tig];
                bl2[1] = KL_[(nf*8+gid)*36 + ks*8 + tig+4];
                mma16f(sc[nf], ah, bh2);
                mma16f(sc[nf], ah, bl2);
            }
        }

        if (kt >= 2 * qt) {    // diagonal tiles
#pragma unroll
            for (int nf = 0; nf < 8; nf++) {
                int cg = kt * 64 + nf * 8 + tig * 2;
                if (cg     > rowg0) sc[nf][0] = -1e30f;
                if (cg + 1 > rowg0) sc[nf][1] = -1e30f;
                if (cg     > rowg1) sc[nf][2] = -1e30f;
                if (cg + 1 > rowg1) sc[nf][3] = -1e30f;
            }
        }

        // online softmax (base-2)
        float mx0 = -1e30f, mx1 = -1e30f;
#pragma unroll
        for (int nf = 0; nf < 8; nf++) {
            mx0 = fmaxf(mx0, fmaxf(sc[nf][0], sc[nf][1]));
            mx1 = fmaxf(mx1, fmaxf(sc[nf][2], sc[nf][3]));
        }
        mx0 = fmaxf(mx0, __shfl_xor_sync(0xffffffffu, mx0, 1));
        mx0 = fmaxf(mx0, __shfl_xor_sync(0xffffffffu, mx0, 2));
        mx1 = fmaxf(mx1, __shfl_xor_sync(0xffffffffu, mx1, 1));
        mx1 = fmaxf(mx1, __shfl_xor_sync(0xffffffffu, mx1, 2));

        float mn0 = fmaxf(m0, mx0), mn1 = fmaxf(m1, mx1);
        float a0 = fexp2(m0 - mn0), a1 = fexp2(m1 - mn1);
        float s0 = 0.f, s1 = 0.f;

#pragma unroll
        for (int nf = 0; nf < 8; nf++) {
            float p00 = fexp2(sc[nf][0] - mn0);
            float p01 = fexp2(sc[nf][1] - mn0);
            float p10 = fexp2(sc[nf][2] - mn1);
            float p11 = fexp2(sc[nf][3] - mn1);
            s0 += p00 + p01;
            s1 += p10 + p11;
            *(__half2*)&P_[(mb+gid)  *36 + nf*4 + tig] = __floats2half2_rn(p00, p01);
            *(__half2*)&P_[(mb+gid+8)*36 + nf*4 + tig] = __floats2half2_rn(p10, p11);
        }
        s0 += __shfl_xor_sync(0xffffffffu, s0, 1);
        s0 += __shfl_xor_sync(0xffffffffu, s0, 2);
        s1 += __shfl_xor_sync(0xffffffffu, s1, 1);
        s1 += __shfl_xor_sync(0xffffffffu, s1, 2);

        l0 = l0 * a0 + s0;
        l1 = l1 * a1 + s1;
        m0 = mn0; m1 = mn1;
#pragma unroll
        for (int nf = 0; nf < 8; nf++) {
            o[nf][0] *= a0; o[nf][1] *= a0;
            o[nf][2] *= a1; o[nf][3] *= a1;
        }
        __syncwarp();

        // O += P V (fp16, V^T layout)
#pragma unroll
        for (int ks = 0; ks < 4; ks++) {
            unsigned ap[4];
            ap[0] = P_[(mb+gid)  *36 + ks*8 + tig];
            ap[1] = P_[(mb+gid+8)*36 + ks*8 + tig];
            ap[2] = P_[(mb+gid)  *36 + ks*8 + tig+4];
            ap[3] = P_[(mb+gid+8)*36 + ks*8 + tig+4];
#pragma unroll
            for (int nf = 0; nf < 8; nf++) {
                unsigned bv[2];
                bv[0] = V_[(nf*8+gid)*36 + ks*8 + tig];
                bv[1] = V_[(nf*8+gid)*36 + ks*8 + tig+4];
                mma16f(o[nf], ap, bv);
            }
        }
        __syncthreads();
    }

    // epilogue: normalize -> fp16, scatter to [B,S,D]
    float il0 = 1.f / l0, il1 = 1.f / l1;
    int b = bh >> 4, h = bh & 15;
#pragma unroll
    for (int nf = 0; nf < 8; nf++) {
        int dh = nf * 8 + tig * 2;
        size_t d0 = ((size_t)(b * S_LEN + rowg0)) * DMODEL + h * 64 + dh;
        size_t d1 = ((size_t)(b * S_LEN + rowg1)) * DMODEL + h * 64 + dh;
        *(__half2*)(g_Oh + d0) = __half2(__float2half(o[nf][0] * il0), __float2half(o[nf][1] * il0));
        *(__half2*)(g_Oh + d1) = __half2(__float2half(o[nf][2] * il1), __float2half(o[nf][3] * il1));
    }
}

// ---------------- launch ----------------
extern "C" void kernel_launch(void* const* d_in, const int* in_sizes, int n_in,
                              void* d_out, int out_size) {
    (void)in_sizes; (void)n_in; (void)out_size;
    const float* x  = (const float*)d_in[0];
    const float* Wq = (const float*)d_in[1];
    const float* Wk = (const float*)d_in[2];
    const float* Wv = (const float*)d_in[3];
    const float* Wo = (const float*)d_in[4];
    float* out = (float*)d_out;

    __half *Xh, *WTH, *WTL, *Oh;
    cudaGetSymbolAddress((void**)&Xh,  g_Xh);
    cudaGetSymbolAddress((void**)&WTH, g_WTH);
    cudaGetSymbolAddress((void**)&WTL, g_WTL);
    cudaGetSymbolAddress((void**)&Oh,  g_Oh);

    cudaFuncSetAttribute(gemm_qkv, cudaFuncAttributeMaxDynamicSharedMemorySize, G_SMEM);
    cudaFuncSetAttribute(gemm_out, cudaFuncAttributeMaxDynamicSharedMemorySize, G_SMEM);
    cudaFuncSetAttribute(attn2_kernel, cudaFuncAttributeMaxDynamicSharedMemorySize, AT_SMEM);

    rope_init_kernel<<<(S_LEN * 32 + 255) / 256, 256>>>();

    const int NX4 = MTOK * DMODEL / 4;
    xh_kernel<<<(NX4 + 255) / 256, 256>>>((const float4*)x, Xh, NX4);

    wtrans_kernel<<<dim3(32, 32, 4), dim3(32, 8)>>>(Wq, Wk, Wv, Wo, WTH, WTL);

    gemm_qkv<<<dim3(DMODEL / 128, MTOK / 128, 3), 256, G_SMEM>>>(Xh, WTH, WTL);

    attn2_kernel<<<dim3(S_LEN / 128, BATCH * NHEAD), 256, AT_SMEM>>>();

    const size_t WSTEP = (size_t)DMODEL * DMODEL;
    gemm_out<<<dim3(DMODEL / 128, MTOK / 128), 256, G_SMEM>>>(Oh, WTH + 3*WSTEP, WTL + 3*WSTEP, out);
}

// round 9
// speedup vs baseline: 4.4861x; 1.1563x over previous
#include <cuda_runtime.h>
#include <cuda_fp16.h>
#include <math.h>

#define S_LEN   2048
#define BATCH   4
#define NHEAD   16
#define DK      64
#define DMODEL  1024
#define MTOK    (BATCH*S_LEN)   // 8192
#define QSCALE  0.18033688011112043f   // log2(e)/8
#define WSC     8.0f
#define WUNSC   0.125f

// ---------------- scratch ----------------
__device__ __half g_Xh [(size_t)MTOK*DMODEL];
__device__ __half g_WTH[(size_t)4*DMODEL*DMODEL];   // 8*W^T [N,K] fp16 hi
__device__ __half g_WTL[(size_t)4*DMODEL*DMODEL];   // fp16 lo
__device__ __half g_Qh [(size_t)MTOK*DMODEL];       // [B,H,S,dk], QSCALE applied
__device__ __half g_KH [(size_t)MTOK*DMODEL];       // [B,H,S,dk]
__device__ __half g_KL [(size_t)MTOK*DMODEL];
__device__ __half g_Vh [(size_t)MTOK*DMODEL];       // TRANSPOSED [B,H,dk,S]
__device__ __half g_Oh [(size_t)MTOK*DMODEL];       // [B,S,D]
__device__ float  g_rc [S_LEN*32];
__device__ float  g_rs [S_LEN*32];

// ---------------- helpers ----------------
__device__ __forceinline__ void mma16f(float* c, const unsigned* a, const unsigned* b) {
    asm volatile(
        "mma.sync.aligned.m16n8k16.row.col.f32.f16.f16.f32 "
        "{%0,%1,%2,%3},{%4,%5,%6,%7},{%8,%9},{%0,%1,%2,%3};\n"
        : "+f"(c[0]), "+f"(c[1]), "+f"(c[2]), "+f"(c[3])
        : "r"(a[0]), "r"(a[1]), "r"(a[2]), "r"(a[3]), "r"(b[0]), "r"(b[1]));
}
__device__ __forceinline__ void ldsm4(unsigned* r, unsigned addr) {
    asm volatile("ldmatrix.sync.aligned.m8n8.x4.shared.b16 {%0,%1,%2,%3}, [%4];"
        : "=r"(r[0]), "=r"(r[1]), "=r"(r[2]), "=r"(r[3]) : "r"(addr));
}
__device__ __forceinline__ unsigned s2u(const void* p) {
    unsigned a;
    asm("{ .reg .u64 t; cvta.to.shared.u64 t, %1; cvt.u32.u64 %0, t; }" : "=r"(a) : "l"(p));
    return a;
}
#define CPA(d, s)  asm volatile("cp.async.cg.shared.global [%0], [%1], 16;\n" :: "r"(d), "l"(s))
#define CPCOMMIT() asm volatile("cp.async.commit_group;\n")
#define CPWAIT0()  asm volatile("cp.async.wait_group 0;\n")
#define CPWAIT1()  asm volatile("cp.async.wait_group 1;\n")

// fast 2^x on fma/alu pipes (no MUFU)
__device__ __forceinline__ float fexp2(float d) {
    d = fmaxf(d, -120.f);
    float r = d + 12582912.f;
    int ib = __float_as_int(r);
    float f = d - (r - 12582912.f);
    float p = 1.f + f*(0.69314718056f + f*(0.240226506959f + f*(0.0555041086648f +
              f*(0.00961812910763f + f*0.00133335581464f))));
    return __int_as_float(__float_as_int(p) + (ib << 23));
}

// ---------------- RoPE table ----------------
__global__ void rope_init_kernel() {
    int i = blockIdx.x * blockDim.x + threadIdx.x;
    if (i >= S_LEN * 32) return;
    int s = i >> 5, j = i & 31;
    double invf = pow(10000.0, -((double)(2*j)) / (double)DK);
    double a = (double)s * invf;
    g_rc[i] = (float)cos(a);
    g_rs[i] = (float)sin(a);
}

// ---------------- x -> fp16 ----------------
__global__ void xh_kernel(const float4* __restrict__ X, __half* __restrict__ H, int n4) {
    int i = blockIdx.x * blockDim.x + threadIdx.x;
    if (i >= n4) return;
    float4 v = X[i];
    __half2* Hp = (__half2*)(H + (size_t)i * 4);
    Hp[0] = __half2(__float2half(v.x), __float2half(v.y));
    Hp[1] = __half2(__float2half(v.z), __float2half(v.w));
}

// ---------------- 4x W[K,N] -> 8*W^T[N,K] fp16 hi/lo ----------------
__global__ void wtrans_kernel(const float* __restrict__ W0, const float* __restrict__ W1,
                              const float* __restrict__ W2, const float* __restrict__ W3,
                              __half* __restrict__ TH, __half* __restrict__ TL) {
    __shared__ float t[32][33];
    int z = blockIdx.z;
    const float* W = (z == 0) ? W0 : (z == 1) ? W1 : (z == 2) ? W2 : W3;
    __half* THz = TH + (size_t)z * DMODEL * DMODEL;
    __half* TLz = TL + (size_t)z * DMODEL * DMODEL;
    int n0 = blockIdx.x * 32, k0 = blockIdx.y * 32;
    int tx = threadIdx.x, ty = threadIdx.y;
#pragma unroll
    for (int j = 0; j < 32; j += 8)
        t[ty + j][tx] = W[(size_t)(k0 + ty + j) * DMODEL + n0 + tx];
    __syncthreads();
#pragma unroll
    for (int j = 0; j < 32; j += 8) {
        float v = t[tx][ty + j] * WSC;
        int n = n0 + ty + j, k = k0 + tx;
        __half hv = __float2half(v);
        THz[(size_t)n * DMODEL + k] = hv;
        TLz[(size_t)n * DMODEL + k] = __float2half(v - __half2float(hv));
    }
}

// ---------------- shared GEMM mainloop: KT=64/stage, ldmatrix fragments ----------------
#define GS 36
#define GW_A  0
#define GW_BH 4608
#define GW_BL 9216
#define GW_STG 13824
#define G_SMEM (2*GW_STG*4)   // 110592 bytes; x2 CTAs = 221184 <= 228KB/SM

__device__ __forceinline__ void gemm_main(const __half* __restrict__ A,
                                          const __half* __restrict__ BH,
                                          const __half* __restrict__ BL,
                                          unsigned sbase, int tid, int bm, int bn,
                                          int wm, int wn, int lane,
                                          float acc[2][8][4]) {
    auto load_stage = [&](int st, int k0) {
        unsigned stb = sbase + (unsigned)(st * GW_STG) * 4u;
#pragma unroll
        for (int i = 0; i < 4; i++) {
            int lin = tid + i * 256;                 // 0..1023: 128 rows x 8 chunks
            int row = lin >> 3, ck = lin & 7;
            unsigned wo = (unsigned)(row * GS + ck * 4) * 4u;
            CPA(stb + GW_A*4u  + wo, A  + (size_t)(bm + row) * DMODEL + k0 + ck * 8);
            CPA(stb + GW_BH*4u + wo, BH + (size_t)(bn + row) * DMODEL + k0 + ck * 8);
            CPA(stb + GW_BL*4u + wo, BL + (size_t)(bn + row) * DMODEL + k0 + ck * 8);
        }
    };

    // per-lane ldmatrix offsets (words)
    const int lrow_a = lane & 15;
    const int lk_a   = (lane >> 4) << 2;            // 0 or 4
    const int bgrp   = lane >> 3;
    const int lrow_b = ((bgrp >> 1) << 3) + (lane & 7);
    const int lk_b   = (bgrp & 1) << 2;

    load_stage(0, 0);
    CPCOMMIT();
    for (int kt = 0; kt < 16; kt++) {
        if (kt + 1 < 16) {
            load_stage((kt + 1) & 1, (kt + 1) * 64);
            CPCOMMIT();
            CPWAIT1();
        } else {
            CPWAIT0();
        }
        __syncthreads();

        unsigned stb = sbase + (unsigned)((kt & 1) * GW_STG) * 4u;
#pragma unroll
        for (int ks = 0; ks < 4; ks++) {
            unsigned ah[2][4];
#pragma unroll
            for (int mf = 0; mf < 2; mf++) {
                int mr = wm * 32 + mf * 16;
                ldsm4(ah[mf], stb + (unsigned)((mr + lrow_a) * GS + ks * 8 + lk_a) * 4u);
            }
#pragma unroll
            for (int nfp = 0; nfp < 4; nfp++) {
                int nc0 = wn * 64 + nfp * 16;
                unsigned boff = (unsigned)((nc0 + lrow_b) * GS + ks * 8 + lk_b) * 4u;
                unsigned bh4[4], bl4[4];
                ldsm4(bh4, stb + GW_BH*4u + boff);
                ldsm4(bl4, stb + GW_BL*4u + boff);
#pragma unroll
                for (int mf = 0; mf < 2; mf++) {
                    mma16f(acc[mf][2*nfp],     ah[mf], bh4);
                    mma16f(acc[mf][2*nfp],     ah[mf], bl4);
                    mma16f(acc[mf][2*nfp + 1], ah[mf], bh4 + 2);
                    mma16f(acc[mf][2*nfp + 1], ah[mf], bl4 + 2);
                }
            }
        }
        __syncthreads();
    }
}

// ---------------- fused QKV GEMM (mode = blockIdx.z: 0=Q, 1=K, 2=V) ----------------
__global__ void __launch_bounds__(256, 2) gemm_qkv(const __half* __restrict__ A,
                                                   const __half* __restrict__ WTH,
                                                   const __half* __restrict__ WTL) {
    extern __shared__ unsigned sm[];
    const int tid = threadIdx.x, lane = tid & 31, warp = tid >> 5;
    const int wm = warp >> 1, wn = warp & 1, gid = lane >> 2, tig = lane & 3;
    const int bm = blockIdx.y * 128, bn = blockIdx.x * 128;
    const int mode = blockIdx.z;
    unsigned sbase = s2u(sm);

    const size_t WSTEP = (size_t)DMODEL * DMODEL;
    const __half* BH = WTH + (size_t)mode * WSTEP;
    const __half* BL = WTL + (size_t)mode * WSTEP;

    float acc[2][8][4];
#pragma unroll
    for (int mf = 0; mf < 2; mf++)
#pragma unroll
        for (int nf = 0; nf < 8; nf++)
#pragma unroll
            for (int c = 0; c < 4; c++) acc[mf][nf][c] = 0.f;

    gemm_main(A, BH, BL, sbase, tid, bm, bn, wm, wn, lane, acc);

#pragma unroll
    for (int mf = 0; mf < 2; mf++) {
#pragma unroll
        for (int nf = 0; nf < 8; nf++) {
            int r0 = bm + wm * 32 + mf * 16 + gid;
            int nc = bn + wn * 64 + nf * 8 + tig * 2;
#pragma unroll
            for (int rr = 0; rr < 2; rr++) {
                int r = r0 + rr * 8;
                float v0 = acc[mf][nf][rr * 2];
                float v1 = acc[mf][nf][rr * 2 + 1];
                int b = r >> 11, s = r & (S_LEN - 1);
                int h = nc >> 6, dh = nc & 63;
                if (mode != 2) {
                    int j = dh >> 1;
                    float cs = g_rc[s * 32 + j], sn = g_rs[s * 32 + j];
                    float t0 = v0 * cs - v1 * sn;
                    float t1 = v1 * cs + v0 * sn;
                    v0 = t0; v1 = t1;
                }
                if (mode == 0) {
                    v0 *= WUNSC * QSCALE; v1 *= WUNSC * QSCALE;
                    size_t dst = ((size_t)(b * NHEAD + h) * S_LEN + s) * DK + dh;
                    *(__half2*)(g_Qh + dst) = __half2(__float2half(v0), __float2half(v1));
                } else if (mode == 1) {
                    v0 *= WUNSC; v1 *= WUNSC;
                    size_t dst = ((size_t)(b * NHEAD + h) * S_LEN + s) * DK + dh;
                    __half h0 = __float2half(v0);
                    __half h1 = __float2half(v1);
                    *(__half2*)(g_KH + dst) = __half2(h0, h1);
                    *(__half2*)(g_KL + dst) = __half2(__float2half(v0 - __half2float(h0)),
                                                      __float2half(v1 - __half2float(h1)));
                } else {  // V: transposed [B,H,dk,S]
                    size_t dstT = ((size_t)((b * NHEAD + h) * DK + dh)) * S_LEN + s;
                    g_Vh[dstT]         = __float2half(v0 * WUNSC);
                    g_Vh[dstT + S_LEN] = __float2half(v1 * WUNSC);
                }
            }
        }
    }
}

// ---------------- output projection GEMM (fp32 out) ----------------
__global__ void __launch_bounds__(256, 2) gemm_out(const __half* __restrict__ A,
                                                   const __half* __restrict__ BH,
                                                   const __half* __restrict__ BL,
                                                   float* __restrict__ C) {
    extern __shared__ unsigned sm[];
    const int tid = threadIdx.x, lane = tid & 31, warp = tid >> 5;
    const int wm = warp >> 1, wn = warp & 1, gid = lane >> 2, tig = lane & 3;
    const int bm = blockIdx.y * 128, bn = blockIdx.x * 128;
    unsigned sbase = s2u(sm);

    float acc[2][8][4];
#pragma unroll
    for (int mf = 0; mf < 2; mf++)
#pragma unroll
        for (int nf = 0; nf < 8; nf++)
#pragma unroll
            for (int c = 0; c < 4; c++) acc[mf][nf][c] = 0.f;

    gemm_main(A, BH, BL, sbase, tid, bm, bn, wm, wn, lane, acc);

#pragma unroll
    for (int mf = 0; mf < 2; mf++) {
#pragma unroll
        for (int nf = 0; nf < 8; nf++) {
            int r0 = bm + wm * 32 + mf * 16 + gid;
            int nc = bn + wn * 64 + nf * 8 + tig * 2;
            C[(size_t)r0 * DMODEL + nc]           = acc[mf][nf][0] * WUNSC;
            C[(size_t)r0 * DMODEL + nc + 1]       = acc[mf][nf][1] * WUNSC;
            C[(size_t)(r0 + 8) * DMODEL + nc]     = acc[mf][nf][2] * WUNSC;
            C[(size_t)(r0 + 8) * DMODEL + nc + 1] = acc[mf][nf][3] * WUNSC;
        }
    }
}

// ---------------- flash attention: Br=128, Bc=64; ldmatrix fragments ----------------
#define AT_Q  0                       // 128 x 36
#define AT_P  4608                    // 128 x 36
#define AT_KH 9216                    // 2 stages x (64 x 36)
#define AT_KL 13824
#define AT_V  18432                   // 2 stages x (64 x 36)  V^T tile [dh][kv]
#define AT_WORDS 23040
#define AT_SMEM (AT_WORDS*4)          // 92160 bytes -> 2 CTAs/SM

__global__ void __launch_bounds__(256, 2) attn2_kernel() {
    extern __shared__ unsigned sm[];
    const int tid = threadIdx.x, lane = tid & 31, warp = tid >> 5;
    const int gid = lane >> 2, tig = lane & 3;
    const int qt = (gridDim.x - 1) - blockIdx.x;
    const int bh = blockIdx.y;
    const int mb = warp * 16;
    unsigned sbase = s2u(sm);

    const __half* Qg  = g_Qh + (size_t)bh * S_LEN * DK + (size_t)qt * 128 * DK;
    const __half* KHg = g_KH + (size_t)bh * S_LEN * DK;
    const __half* KLg = g_KL + (size_t)bh * S_LEN * DK;
    const __half* Vtg = g_Vh + (size_t)bh * S_LEN * DK;   // [dk][S]

    // ldmatrix per-lane offsets
    const int lrow_a = lane & 15;
    const int lk_a   = (lane >> 4) << 2;
    const int bgrp   = lane >> 3;
    const int lrow_b = ((bgrp >> 1) << 3) + (lane & 7);
    const int lk_b   = (bgrp & 1) << 2;

#pragma unroll
    for (int i = 0; i < 4; i++) {
        int lin = tid + i * 256;
        int row = lin >> 3, ck = lin & 7;
        CPA(sbase + AT_Q*4u + (unsigned)(row * 36 + ck * 4) * 4u, Qg + row * 64 + ck * 8);
    }

    auto load_kv = [&](int st, int kt) {
        size_t koff = (size_t)kt * 64 * DK;
#pragma unroll
        for (int i = 0; i < 2; i++) {
            int lin = tid + i * 256;
            int row = lin >> 3, ck = lin & 7;
            unsigned wo = (unsigned)(row * 36 + ck * 4) * 4u;
            CPA(sbase + (AT_KH + st*2304)*4u + wo, KHg + koff + row * 64 + ck * 8);
            CPA(sbase + (AT_KL + st*2304)*4u + wo, KLg + koff + row * 64 + ck * 8);
            CPA(sbase + (AT_V  + st*2304)*4u + wo, Vtg + (size_t)row * S_LEN + kt * 64 + ck * 8);
        }
    };

    const int rowg0 = qt * 128 + mb + gid;
    const int rowg1 = rowg0 + 8;
    float m0 = -1e30f, m1 = -1e30f, l0 = 0.f, l1 = 0.f;
    float o[8][4];
#pragma unroll
    for (int nf = 0; nf < 8; nf++)
#pragma unroll
        for (int c = 0; c < 4; c++) o[nf][c] = 0.f;

    const int kmax = 2 * qt + 2;
    load_kv(0, 0);
    CPCOMMIT();

    for (int kt = 0; kt < kmax; kt++) {
        if (kt + 1 < kmax) load_kv((kt + 1) & 1, kt + 1);
        CPCOMMIT();
        CPWAIT1();
        __syncthreads();

        unsigned qb = sbase + AT_Q * 4u;
        unsigned pb = sbase + AT_P * 4u;
        unsigned khb = sbase + (AT_KH + (kt & 1) * 2304) * 4u;
        unsigned klb = sbase + (AT_KL + (kt & 1) * 2304) * 4u;
        unsigned vb  = sbase + (AT_V  + (kt & 1) * 2304) * 4u;
        unsigned* P_ = sm + AT_P;

        // S = Q K^T (fp16 2-term)
        float sc[8][4];
#pragma unroll
        for (int nf = 0; nf < 8; nf++)
#pragma unroll
            for (int c = 0; c < 4; c++) sc[nf][c] = 0.f;

#pragma unroll
        for (int ks = 0; ks < 4; ks++) {
            unsigned ah[4];
            ldsm4(ah, qb + (unsigned)((mb + lrow_a) * 36 + ks * 8 + lk_a) * 4u);
#pragma unroll
            for (int nfp = 0; nfp < 4; nfp++) {
                unsigned boff = (unsigned)((nfp * 16 + lrow_b) * 36 + ks * 8 + lk_b) * 4u;
                unsigned kh4[4], kl4[4];
                ldsm4(kh4, khb + boff);
                ldsm4(kl4, klb + boff);
                mma16f(sc[2*nfp],     ah, kh4);
                mma16f(sc[2*nfp],     ah, kl4);
                mma16f(sc[2*nfp + 1], ah, kh4 + 2);
                mma16f(sc[2*nfp + 1], ah, kl4 + 2);
            }
        }

        if (kt >= 2 * qt) {    // diagonal tiles
#pragma unroll
            for (int nf = 0; nf < 8; nf++) {
                int cg = kt * 64 + nf * 8 + tig * 2;
                if (cg     > rowg0) sc[nf][0] = -1e30f;
                if (cg + 1 > rowg0) sc[nf][1] = -1e30f;
                if (cg     > rowg1) sc[nf][2] = -1e30f;
                if (cg + 1 > rowg1) sc[nf][3] = -1e30f;
            }
        }

        // online softmax (base-2)
        float mx0 = -1e30f, mx1 = -1e30f;
#pragma unroll
        for (int nf = 0; nf < 8; nf++) {
            mx0 = fmaxf(mx0, fmaxf(sc[nf][0], sc[nf][1]));
            mx1 = fmaxf(mx1, fmaxf(sc[nf][2], sc[nf][3]));
        }
        mx0 = fmaxf(mx0, __shfl_xor_sync(0xffffffffu, mx0, 1));
        mx0 = fmaxf(mx0, __shfl_xor_sync(0xffffffffu, mx0, 2));
        mx1 = fmaxf(mx1, __shfl_xor_sync(0xffffffffu, mx1, 1));
        mx1 = fmaxf(mx1, __shfl_xor_sync(0xffffffffu, mx1, 2));

        float mn0 = fmaxf(m0, mx0), mn1 = fmaxf(m1, mx1);
        float a0 = fexp2(m0 - mn0), a1 = fexp2(m1 - mn1);
        float s0 = 0.f, s1 = 0.f;

#pragma unroll
        for (int nf = 0; nf < 8; nf++) {
            float p00 = fexp2(sc[nf][0] - mn0);
            float p01 = fexp2(sc[nf][1] - mn0);
            float p10 = fexp2(sc[nf][2] - mn1);
            float p11 = fexp2(sc[nf][3] - mn1);
            s0 += p00 + p01;
            s1 += p10 + p11;
            *(__half2*)&P_[(mb+gid)  *36 + nf*4 + tig] = __floats2half2_rn(p00, p01);
            *(__half2*)&P_[(mb+gid+8)*36 + nf*4 + tig] = __floats2half2_rn(p10, p11);
        }
        s0 += __shfl_xor_sync(0xffffffffu, s0, 1);
        s0 += __shfl_xor_sync(0xffffffffu, s0, 2);
        s1 += __shfl_xor_sync(0xffffffffu, s1, 1);
        s1 += __shfl_xor_sync(0xffffffffu, s1, 2);

        l0 = l0 * a0 + s0;
        l1 = l1 * a1 + s1;
        m0 = mn0; m1 = mn1;
#pragma unroll
        for (int nf = 0; nf < 8; nf++) {
            o[nf][0] *= a0; o[nf][1] *= a0;
            o[nf][2] *= a1; o[nf][3] *= a1;
        }
        __syncwarp();

        // O += P V (fp16, V^T layout)
#pragma unroll
        for (int ks = 0; ks < 4; ks++) {
            unsigned ap[4];
            ldsm4(ap, pb + (unsigned)((mb + lrow_a) * 36 + ks * 8 + lk_a) * 4u);
#pragma unroll
            for (int nfp = 0; nfp < 4; nfp++) {
                unsigned bv4[4];
                ldsm4(bv4, vb + (unsigned)((nfp * 16 + lrow_b) * 36 + ks * 8 + lk_b) * 4u);
                mma16f(o[2*nfp],     ap, bv4);
                mma16f(o[2*nfp + 1], ap, bv4 + 2);
            }
        }
        __syncthreads();
    }

    // epilogue: normalize -> fp16, scatter to [B,S,D]
    float il0 = 1.f / l0, il1 = 1.f / l1;
    int b = bh >> 4, h = bh & 15;
#pragma unroll
    for (int nf = 0; nf < 8; nf++) {
        int dh = nf * 8 + tig * 2;
        size_t d0 = ((size_t)(b * S_LEN + rowg0)) * DMODEL + h * 64 + dh;
        size_t d1 = ((size_t)(b * S_LEN + rowg1)) * DMODEL + h * 64 + dh;
        *(__half2*)(g_Oh + d0) = __half2(__float2half(o[nf][0] * il0), __float2half(o[nf][1] * il0));
        *(__half2*)(g_Oh + d1) = __half2(__float2half(o[nf][2] * il1), __float2half(o[nf][3] * il1));
    }
}

// ---------------- launch ----------------
extern "C" void kernel_launch(void* const* d_in, const int* in_sizes, int n_in,
                              void* d_out, int out_size) {
    (void)in_sizes; (void)n_in; (void)out_size;
    const float* x  = (const float*)d_in[0];
    const float* Wq = (const float*)d_in[1];
    const float* Wk = (const float*)d_in[2];
    const float* Wv = (const float*)d_in[3];
    const float* Wo = (const float*)d_in[4];
    float* out = (float*)d_out;

    __half *Xh, *WTH, *WTL, *Oh;
    cudaGetSymbolAddress((void**)&Xh,  g_Xh);
    cudaGetSymbolAddress((void**)&WTH, g_WTH);
    cudaGetSymbolAddress((void**)&WTL, g_WTL);
    cudaGetSymbolAddress((void**)&Oh,  g_Oh);

    cudaFuncSetAttribute(gemm_qkv, cudaFuncAttributeMaxDynamicSharedMemorySize, G_SMEM);
    cudaFuncSetAttribute(gemm_out, cudaFuncAttributeMaxDynamicSharedMemorySize, G_SMEM);
    cudaFuncSetAttribute(attn2_kernel, cudaFuncAttributeMaxDynamicSharedMemorySize, AT_SMEM);

    rope_init_kernel<<<(S_LEN * 32 + 255) / 256, 256>>>();

    const int NX4 = MTOK * DMODEL / 4;
    xh_kernel<<<(NX4 + 255) / 256, 256>>>((const float4*)x, Xh, NX4);

    wtrans_kernel<<<dim3(32, 32, 4), dim3(32, 8)>>>(Wq, Wk, Wv, Wo, WTH, WTL);

    gemm_qkv<<<dim3(DMODEL / 128, MTOK / 128, 3), 256, G_SMEM>>>(Xh, WTH, WTL);

    attn2_kernel<<<dim3(S_LEN / 128, BATCH * NHEAD), 256, AT_SMEM>>>();

    const size_t WSTEP = (size_t)DMODEL * DMODEL;
    gemm_out<<<dim3(DMODEL / 128, MTOK / 128), 256, G_SMEM>>>(Oh, WTH + 3*WSTEP, WTL + 3*WSTEP, out);
}

// round 10
// speedup vs baseline: 4.5575x; 1.0159x over previous
#include <cuda_runtime.h>
#include <cuda_fp16.h>
#include <math.h>

#define S_LEN   2048
#define BATCH   4
#define NHEAD   16
#define DK      64
#define DMODEL  1024
#define MTOK    (BATCH*S_LEN)   // 8192
#define QSCALE  0.18033688011112043f   // log2(e)/8
#define WSC     8.0f
#define WUNSC   0.125f

// ---------------- scratch ----------------
__device__ __half g_Xh [(size_t)MTOK*DMODEL];
__device__ __half g_WTH[(size_t)4*DMODEL*DMODEL];   // 8*W^T [N,K] fp16 hi
__device__ __half g_WTL[(size_t)4*DMODEL*DMODEL];   // fp16 lo
__device__ __half g_Qh [(size_t)MTOK*DMODEL];       // [B,H,S,dk], QSCALE applied
__device__ __half g_KH [(size_t)MTOK*DMODEL];       // [B,H,S,dk]
__device__ __half g_KL [(size_t)MTOK*DMODEL];
__device__ __half g_Vh [(size_t)MTOK*DMODEL];       // TRANSPOSED [B,H,dk,S]
__device__ __half g_Oh [(size_t)MTOK*DMODEL];       // [B,S,D]
__device__ float  g_rc [S_LEN*32];
__device__ float  g_rs [S_LEN*32];

// ---------------- helpers ----------------
__device__ __forceinline__ void mma16f(float* c, const unsigned* a, const unsigned* b) {
    asm volatile(
        "mma.sync.aligned.m16n8k16.row.col.f32.f16.f16.f32 "
        "{%0,%1,%2,%3},{%4,%5,%6,%7},{%8,%9},{%0,%1,%2,%3};\n"
        : "+f"(c[0]), "+f"(c[1]), "+f"(c[2]), "+f"(c[3])
        : "r"(a[0]), "r"(a[1]), "r"(a[2]), "r"(a[3]), "r"(b[0]), "r"(b[1]));
}
__device__ __forceinline__ void ldsm4(unsigned* r, unsigned addr) {
    asm volatile("ldmatrix.sync.aligned.m8n8.x4.shared.b16 {%0,%1,%2,%3}, [%4];"
        : "=r"(r[0]), "=r"(r[1]), "=r"(r[2]), "=r"(r[3]) : "r"(addr));
}
__device__ __forceinline__ unsigned s2u(const void* p) {
    unsigned a;
    asm("{ .reg .u64 t; cvta.to.shared.u64 t, %1; cvt.u32.u64 %0, t; }" : "=r"(a) : "l"(p));
    return a;
}
#define CPA(d, s)  asm volatile("cp.async.cg.shared.global [%0], [%1], 16;\n" :: "r"(d), "l"(s))
#define CPCOMMIT() asm volatile("cp.async.commit_group;\n")
#define CPWAIT0()  asm volatile("cp.async.wait_group 0;\n")

// fast 2^x on fma/alu pipes (no MUFU)
__device__ __forceinline__ float fexp2(float d) {
    d = fmaxf(d, -120.f);
    float r = d + 12582912.f;
    int ib = __float_as_int(r);
    float f = d - (r - 12582912.f);
    float p = 1.f + f*(0.69314718056f + f*(0.240226506959f + f*(0.0555041086648f +
              f*(0.00961812910763f + f*0.00133335581464f))));
    return __int_as_float(__float_as_int(p) + (ib << 23));
}

// ---------------- RoPE table ----------------
__global__ void rope_init_kernel() {
    int i = blockIdx.x * blockDim.x + threadIdx.x;
    if (i >= S_LEN * 32) return;
    int s = i >> 5, j = i & 31;
    double invf = pow(10000.0, -((double)(2*j)) / (double)DK);
    double a = (double)s * invf;
    g_rc[i] = (float)cos(a);
    g_rs[i] = (float)sin(a);
}

// ---------------- x -> fp16 ----------------
__global__ void xh_kernel(const float4* __restrict__ X, __half* __restrict__ H, int n4) {
    int i = blockIdx.x * blockDim.x + threadIdx.x;
    if (i >= n4) return;
    float4 v = X[i];
    __half2* Hp = (__half2*)(H + (size_t)i * 4);
    Hp[0] = __half2(__float2half(v.x), __float2half(v.y));
    Hp[1] = __half2(__float2half(v.z), __float2half(v.w));
}

// ---------------- 4x W[K,N] -> 8*W^T[N,K] fp16 hi/lo ----------------
__global__ void wtrans_kernel(const float* __restrict__ W0, const float* __restrict__ W1,
                              const float* __restrict__ W2, const float* __restrict__ W3,
                              __half* __restrict__ TH, __half* __restrict__ TL) {
    __shared__ float t[32][33];
    int z = blockIdx.z;
    const float* W = (z == 0) ? W0 : (z == 1) ? W1 : (z == 2) ? W2 : W3;
    __half* THz = TH + (size_t)z * DMODEL * DMODEL;
    __half* TLz = TL + (size_t)z * DMODEL * DMODEL;
    int n0 = blockIdx.x * 32, k0 = blockIdx.y * 32;
    int tx = threadIdx.x, ty = threadIdx.y;
#pragma unroll
    for (int j = 0; j < 32; j += 8)
        t[ty + j][tx] = W[(size_t)(k0 + ty + j) * DMODEL + n0 + tx];
    __syncthreads();
#pragma unroll
    for (int j = 0; j < 32; j += 8) {
        float v = t[tx][ty + j] * WSC;
        int n = n0 + ty + j, k = k0 + tx;
        __half hv = __float2half(v);
        THz[(size_t)n * DMODEL + k] = hv;
        TLz[(size_t)n * DMODEL + k] = __float2half(v - __half2float(hv));
    }
}

// ---------------- shared GEMM mainloop: KT=64/stage, 2x4 warp grid, 1 barrier/stage ----------------
#define GS 36
#define GW_A  0
#define GW_BH 4608
#define GW_BL 9216
#define GW_STG 13824
#define G_SMEM (2*GW_STG*4)   // 110592 bytes; x2 CTAs = 221184 <= 228KB/SM

__device__ __forceinline__ void gemm_main(const __half* __restrict__ A,
                                          const __half* __restrict__ BH,
                                          const __half* __restrict__ BL,
                                          unsigned sbase, int tid, int bm, int bn,
                                          int wm, int wn, int lane,
                                          float acc[4][4][4]) {
    auto load_stage = [&](int st, int k0) {
        unsigned stb = sbase + (unsigned)(st * GW_STG) * 4u;
#pragma unroll
        for (int i = 0; i < 4; i++) {
            int lin = tid + i * 256;                 // 0..1023: 128 rows x 8 chunks
            int row = lin >> 3, ck = lin & 7;
            unsigned wo = (unsigned)(row * GS + ck * 4) * 4u;
            CPA(stb + GW_A*4u  + wo, A  + (size_t)(bm + row) * DMODEL + k0 + ck * 8);
            CPA(stb + GW_BH*4u + wo, BH + (size_t)(bn + row) * DMODEL + k0 + ck * 8);
            CPA(stb + GW_BL*4u + wo, BL + (size_t)(bn + row) * DMODEL + k0 + ck * 8);
        }
    };

    // per-lane ldmatrix offsets (words)
    const int lrow_a = lane & 15;
    const int lk_a   = (lane >> 4) << 2;            // 0 or 4
    const int bgrp   = lane >> 3;
    const int lrow_b = ((bgrp >> 1) << 3) + (lane & 7);
    const int lk_b   = (bgrp & 1) << 2;

    load_stage(0, 0);
    CPCOMMIT();
    for (int kt = 0; kt < 16; kt++) {
        CPWAIT0();
        __syncthreads();
        if (kt + 1 < 16) {
            load_stage((kt + 1) & 1, (kt + 1) * 64);
            CPCOMMIT();
        }

        unsigned stb = sbase + (unsigned)((kt & 1) * GW_STG) * 4u;
#pragma unroll
        for (int ks = 0; ks < 4; ks++) {
            unsigned ah[4][4];
#pragma unroll
            for (int mf = 0; mf < 4; mf++) {
                int mr = wm * 64 + mf * 16;
                ldsm4(ah[mf], stb + (unsigned)((mr + lrow_a) * GS + ks * 8 + lk_a) * 4u);
            }
#pragma unroll
            for (int nfp = 0; nfp < 2; nfp++) {
                int nc0 = wn * 32 + nfp * 16;
                unsigned boff = (unsigned)((nc0 + lrow_b) * GS + ks * 8 + lk_b) * 4u;
                unsigned bh4[4], bl4[4];
                ldsm4(bh4, stb + GW_BH*4u + boff);
                ldsm4(bl4, stb + GW_BL*4u + boff);
#pragma unroll
                for (int mf = 0; mf < 4; mf++) {
                    mma16f(acc[mf][2*nfp],     ah[mf], bh4);
                    mma16f(acc[mf][2*nfp],     ah[mf], bl4);
                    mma16f(acc[mf][2*nfp + 1], ah[mf], bh4 + 2);
                    mma16f(acc[mf][2*nfp + 1], ah[mf], bl4 + 2);
                }
            }
        }
    }
}

// ---------------- fused QKV GEMM (mode = blockIdx.z: 0=Q, 1=K, 2=V) ----------------
__global__ void __launch_bounds__(256, 2) gemm_qkv(const __half* __restrict__ A,
                                                   const __half* __restrict__ WTH,
                                                   const __half* __restrict__ WTL) {
    extern __shared__ unsigned sm[];
    const int tid = threadIdx.x, lane = tid & 31, warp = tid >> 5;
    const int wm = warp >> 2, wn = warp & 3, gid = lane >> 2, tig = lane & 3;
    const int bm = blockIdx.y * 128, bn = blockIdx.x * 128;
    const int mode = blockIdx.z;
    unsigned sbase = s2u(sm);

    const size_t WSTEP = (size_t)DMODEL * DMODEL;
    const __half* BH = WTH + (size_t)mode * WSTEP;
    const __half* BL = WTL + (size_t)mode * WSTEP;

    float acc[4][4][4];
#pragma unroll
    for (int mf = 0; mf < 4; mf++)
#pragma unroll
        for (int nf = 0; nf < 4; nf++)
#pragma unroll
            for (int c = 0; c < 4; c++) acc[mf][nf][c] = 0.f;

    gemm_main(A, BH, BL, sbase, tid, bm, bn, wm, wn, lane, acc);

#pragma unroll
    for (int mf = 0; mf < 4; mf++) {
#pragma unroll
        for (int nf = 0; nf < 4; nf++) {
            int r0 = bm + wm * 64 + mf * 16 + gid;
            int nc = bn + wn * 32 + nf * 8 + tig * 2;
#pragma unroll
            for (int rr = 0; rr < 2; rr++) {
                int r = r0 + rr * 8;
                float v0 = acc[mf][nf][rr * 2];
                float v1 = acc[mf][nf][rr * 2 + 1];
                int b = r >> 11, s = r & (S_LEN - 1);
                int h = nc >> 6, dh = nc & 63;
                if (mode != 2) {
                    int j = dh >> 1;
                    float cs = g_rc[s * 32 + j], sn = g_rs[s * 32 + j];
                    float t0 = v0 * cs - v1 * sn;
                    float t1 = v1 * cs + v0 * sn;
                    v0 = t0; v1 = t1;
                }
                if (mode == 0) {
                    v0 *= WUNSC * QSCALE; v1 *= WUNSC * QSCALE;
                    size_t dst = ((size_t)(b * NHEAD + h) * S_LEN + s) * DK + dh;
                    *(__half2*)(g_Qh + dst) = __half2(__float2half(v0), __float2half(v1));
                } else if (mode == 1) {
                    v0 *= WUNSC; v1 *= WUNSC;
                    size_t dst = ((size_t)(b * NHEAD + h) * S_LEN + s) * DK + dh;
                    __half h0 = __float2half(v0);
                    __half h1 = __float2half(v1);
                    *(__half2*)(g_KH + dst) = __half2(h0, h1);
                    *(__half2*)(g_KL + dst) = __half2(__float2half(v0 - __half2float(h0)),
                                                      __float2half(v1 - __half2float(h1)));
                } else {  // V: transposed [B,H,dk,S]
                    size_t dstT = ((size_t)((b * NHEAD + h) * DK + dh)) * S_LEN + s;
                    g_Vh[dstT]         = __float2half(v0 * WUNSC);
                    g_Vh[dstT + S_LEN] = __float2half(v1 * WUNSC);
                }
            }
        }
    }
}

// ---------------- output projection GEMM (fp32 out) ----------------
__global__ void __launch_bounds__(256, 2) gemm_out(const __half* __restrict__ A,
                                                   const __half* __restrict__ BH,
                                                   const __half* __restrict__ BL,
                                                   float* __restrict__ C) {
    extern __shared__ unsigned sm[];
    const int tid = threadIdx.x, lane = tid & 31, warp = tid >> 5;
    const int wm = warp >> 2, wn = warp & 3, gid = lane >> 2, tig = lane & 3;
    const int bm = blockIdx.y * 128, bn = blockIdx.x * 128;
    unsigned sbase = s2u(sm);

    float acc[4][4][4];
#pragma unroll
    for (int mf = 0; mf < 4; mf++)
#pragma unroll
        for (int nf = 0; nf < 4; nf++)
#pragma unroll
            for (int c = 0; c < 4; c++) acc[mf][nf][c] = 0.f;

    gemm_main(A, BH, BL, sbase, tid, bm, bn, wm, wn, lane, acc);

#pragma unroll
    for (int mf = 0; mf < 4; mf++) {
#pragma unroll
        for (int nf = 0; nf < 4; nf++) {
            int r0 = bm + wm * 64 + mf * 16 + gid;
            int nc = bn + wn * 32 + nf * 8 + tig * 2;
            C[(size_t)r0 * DMODEL + nc]           = acc[mf][nf][0] * WUNSC;
            C[(size_t)r0 * DMODEL + nc + 1]       = acc[mf][nf][1] * WUNSC;
            C[(size_t)(r0 + 8) * DMODEL + nc]     = acc[mf][nf][2] * WUNSC;
            C[(size_t)(r0 + 8) * DMODEL + nc + 1] = acc[mf][nf][3] * WUNSC;
        }
    }
}

// ---------------- flash attention: Br=128, Bc=64; 1 barrier/stage ----------------
#define AT_Q  0                       // 128 x 36
#define AT_P  4608                    // 128 x 36
#define AT_KH 9216                    // 2 stages x (64 x 36)
#define AT_KL 13824
#define AT_V  18432                   // 2 stages x (64 x 36)  V^T tile [dh][kv]
#define AT_WORDS 23040
#define AT_SMEM (AT_WORDS*4)          // 92160 bytes -> 2 CTAs/SM

__global__ void __launch_bounds__(256, 2) attn2_kernel() {
    extern __shared__ unsigned sm[];
    const int tid = threadIdx.x, lane = tid & 31, warp = tid >> 5;
    const int gid = lane >> 2, tig = lane & 3;
    const int qt = (gridDim.x - 1) - blockIdx.x;
    const int bh = blockIdx.y;
    const int mb = warp * 16;
    unsigned sbase = s2u(sm);

    const __half* Qg  = g_Qh + (size_t)bh * S_LEN * DK + (size_t)qt * 128 * DK;
    const __half* KHg = g_KH + (size_t)bh * S_LEN * DK;
    const __half* KLg = g_KL + (size_t)bh * S_LEN * DK;
    const __half* Vtg = g_Vh + (size_t)bh * S_LEN * DK;   // [dk][S]

    // ldmatrix per-lane offsets
    const int lrow_a = lane & 15;
    const int lk_a   = (lane >> 4) << 2;
    const int bgrp   = lane >> 3;
    const int lrow_b = ((bgrp >> 1) << 3) + (lane & 7);
    const int lk_b   = (bgrp & 1) << 2;

#pragma unroll
    for (int i = 0; i < 4; i++) {
        int lin = tid + i * 256;
        int row = lin >> 3, ck = lin & 7;
        CPA(sbase + AT_Q*4u + (unsigned)(row * 36 + ck * 4) * 4u, Qg + row * 64 + ck * 8);
    }

    auto load_kv = [&](int st, int kt) {
        size_t koff = (size_t)kt * 64 * DK;
#pragma unroll
        for (int i = 0; i < 2; i++) {
            int lin = tid + i * 256;
            int row = lin >> 3, ck = lin & 7;
            unsigned wo = (unsigned)(row * 36 + ck * 4) * 4u;
            CPA(sbase + (AT_KH + st*2304)*4u + wo, KHg + koff + row * 64 + ck * 8);
            CPA(sbase + (AT_KL + st*2304)*4u + wo, KLg + koff + row * 64 + ck * 8);
            CPA(sbase + (AT_V  + st*2304)*4u + wo, Vtg + (size_t)row * S_LEN + kt * 64 + ck * 8);
        }
    };

    const int rowg0 = qt * 128 + mb + gid;
    const int rowg1 = rowg0 + 8;
    float m0 = -1e30f, m1 = -1e30f, l0 = 0.f, l1 = 0.f;
    float o[8][4];
#pragma unroll
    for (int nf = 0; nf < 8; nf++)
#pragma unroll
        for (int c = 0; c < 4; c++) o[nf][c] = 0.f;

    const int kmax = 2 * qt + 2;
    load_kv(0, 0);
    CPCOMMIT();

    for (int kt = 0; kt < kmax; kt++) {
        CPWAIT0();
        __syncthreads();
        if (kt + 1 < kmax) {
            load_kv((kt + 1) & 1, kt + 1);
            CPCOMMIT();
        }

        unsigned qb = sbase + AT_Q * 4u;
        unsigned pb = sbase + AT_P * 4u;
        unsigned khb = sbase + (AT_KH + (kt & 1) * 2304) * 4u;
        unsigned klb = sbase + (AT_KL + (kt & 1) * 2304) * 4u;
        unsigned vb  = sbase + (AT_V  + (kt & 1) * 2304) * 4u;
        unsigned* P_ = sm + AT_P;

        // S = Q K^T (fp16 2-term)
        float sc[8][4];
#pragma unroll
        for (int nf = 0; nf < 8; nf++)
#pragma unroll
            for (int c = 0; c < 4; c++) sc[nf][c] = 0.f;

#pragma unroll
        for (int ks = 0; ks < 4; ks++) {
            unsigned ah[4];
            ldsm4(ah, qb + (unsigned)((mb + lrow_a) * 36 + ks * 8 + lk_a) * 4u);
#pragma unroll
            for (int nfp = 0; nfp < 4; nfp++) {
                unsigned boff = (unsigned)((nfp * 16 + lrow_b) * 36 + ks * 8 + lk_b) * 4u;
                unsigned kh4[4], kl4[4];
                ldsm4(kh4, khb + boff);
                ldsm4(kl4, klb + boff);
                mma16f(sc[2*nfp],     ah, kh4);
                mma16f(sc[2*nfp],     ah, kl4);
                mma16f(sc[2*nfp + 1], ah, kh4 + 2);
                mma16f(sc[2*nfp + 1], ah, kl4 + 2);
            }
        }

        if (kt >= 2 * qt) {    // diagonal tiles
#pragma unroll
            for (int nf = 0; nf < 8; nf++) {
                int cg = kt * 64 + nf * 8 + tig * 2;
                if (cg     > rowg0) sc[nf][0] = -1e30f;
                if (cg + 1 > rowg0) sc[nf][1] = -1e30f;
                if (cg     > rowg1) sc[nf][2] = -1e30f;
                if (cg + 1 > rowg1) sc[nf][3] = -1e30f;
            }
        }

        // online softmax (base-2)
        float mx0 = -1e30f, mx1 = -1e30f;
#pragma unroll
        for (int nf = 0; nf < 8; nf++) {
            mx0 = fmaxf(mx0, fmaxf(sc[nf][0], sc[nf][1]));
            mx1 = fmaxf(mx1, fmaxf(sc[nf][2], sc[nf][3]));
        }
        mx0 = fmaxf(mx0, __shfl_xor_sync(0xffffffffu, mx0, 1));
        mx0 = fmaxf(mx0, __shfl_xor_sync(0xffffffffu, mx0, 2));
        mx1 = fmaxf(mx1, __shfl_xor_sync(0xffffffffu, mx1, 1));
        mx1 = fmaxf(mx1, __shfl_xor_sync(0xffffffffu, mx1, 2));

        float mn0 = fmaxf(m0, mx0), mn1 = fmaxf(m1, mx1);
        float a0 = fexp2(m0 - mn0), a1 = fexp2(m1 - mn1);
        float s0 = 0.f, s1 = 0.f;

#pragma unroll
        for (int nf = 0; nf < 8; nf++) {
            float p00 = fexp2(sc[nf][0] - mn0);
            float p01 = fexp2(sc[nf][1] - mn0);
            float p10 = fexp2(sc[nf][2] - mn1);
            float p11 = fexp2(sc[nf][3] - mn1);
            s0 += p00 + p01;
            s1 += p10 + p11;
            *(__half2*)&P_[(mb+gid)  *36 + nf*4 + tig] = __floats2half2_rn(p00, p01);
            *(__half2*)&P_[(mb+gid+8)*36 + nf*4 + tig] = __floats2half2_rn(p10, p11);
        }
        s0 += __shfl_xor_sync(0xffffffffu, s0, 1);
        s0 += __shfl_xor_sync(0xffffffffu, s0, 2);
        s1 += __shfl_xor_sync(0xffffffffu, s1, 1);
        s1 += __shfl_xor_sync(0xffffffffu, s1, 2);

        l0 = l0 * a0 + s0;
        l1 = l1 * a1 + s1;
        m0 = mn0; m1 = mn1;
#pragma unroll
        for (int nf = 0; nf < 8; nf++) {
            o[nf][0] *= a0; o[nf][1] *= a0;
            o[nf][2] *= a1; o[nf][3] *= a1;
        }
        __syncwarp();

        // O += P V (fp16, V^T layout; P is warp-private rows)
#pragma unroll
        for (int ks = 0; ks < 4; ks++) {
            unsigned ap[4];
            ldsm4(ap, pb + (unsigned)((mb + lrow_a) * 36 + ks * 8 + lk_a) * 4u);
#pragma unroll
            for (int nfp = 0; nfp < 4; nfp++) {
                unsigned bv4[4];
                ldsm4(bv4, vb + (unsigned)((nfp * 16 + lrow_b) * 36 + ks * 8 + lk_b) * 4u);
                mma16f(o[2*nfp],     ap, bv4);
                mma16f(o[2*nfp + 1], ap, bv4 + 2);
            }
        }
        __syncwarp();
    }

    // epilogue: normalize -> fp16, scatter to [B,S,D]
    float il0 = 1.f / l0, il1 = 1.f / l1;
    int b = bh >> 4, h = bh & 15;
#pragma unroll
    for (int nf = 0; nf < 8; nf++) {
        int dh = nf * 8 + tig * 2;
        size_t d0 = ((size_t)(b * S_LEN + rowg0)) * DMODEL + h * 64 + dh;
        size_t d1 = ((size_t)(b * S_LEN + rowg1)) * DMODEL + h * 64 + dh;
        *(__half2*)(g_Oh + d0) = __half2(__float2half(o[nf][0] * il0), __float2half(o[nf][1] * il0));
        *(__half2*)(g_Oh + d1) = __half2(__float2half(o[nf][2] * il1), __float2half(o[nf][3] * il1));
    }
}

// ---------------- launch ----------------
extern "C" void kernel_launch(void* const* d_in, const int* in_sizes, int n_in,
                              void* d_out, int out_size) {
    (void)in_sizes; (void)n_in; (void)out_size;
    const float* x  = (const float*)d_in[0];
    const float* Wq = (const float*)d_in[1];
    const float* Wk = (const float*)d_in[2];
    const float* Wv = (const float*)d_in[3];
    const float* Wo = (const float*)d_in[4];
    float* out = (float*)d_out;

    __half *Xh, *WTH, *WTL, *Oh;
    cudaGetSymbolAddress((void**)&Xh,  g_Xh);
    cudaGetSymbolAddress((void**)&WTH, g_WTH);
    cudaGetSymbolAddress((void**)&WTL, g_WTL);
    cudaGetSymbolAddress((void**)&Oh,  g_Oh);

    cudaFuncSetAttribute(gemm_qkv, cudaFuncAttributeMaxDynamicSharedMemorySize, G_SMEM);
    cudaFuncSetAttribute(gemm_out, cudaFuncAttributeMaxDynamicSharedMemorySize, G_SMEM);
    cudaFuncSetAttribute(attn2_kernel, cudaFuncAttributeMaxDynamicSharedMemorySize, AT_SMEM);

    rope_init_kernel<<<(S_LEN * 32 + 255) / 256, 256>>>();

    const int NX4 = MTOK * DMODEL / 4;
    xh_kernel<<<(NX4 + 255) / 256, 256>>>((const float4*)x, Xh, NX4);

    wtrans_kernel<<<dim3(32, 32, 4), dim3(32, 8)>>>(Wq, Wk, Wv, Wo, WTH, WTL);

    gemm_qkv<<<dim3(DMODEL / 128, MTOK / 128, 3), 256, G_SMEM>>>(Xh, WTH, WTL);

    attn2_kernel<<<dim3(S_LEN / 128, BATCH * NHEAD), 256, AT_SMEM>>>();

    const size_t WSTEP = (size_t)DMODEL * DMODEL;
    gemm_out<<<dim3(DMODEL / 128, MTOK / 128), 256, G_SMEM>>>(Oh, WTH + 3*WSTEP, WTL + 3*WSTEP, out);
}